// round 1
// baseline (speedup 1.0000x reference)
#include <cuda_runtime.h>
#include <math.h>

#define BB 8
#define SS 512
#define HH 1024
#define NHD 16
#define DD 64
#define MM (BB*SS)      // 4096
#define BH (BB*NHD)     // 128
#define CD 192          // concatenated head dim (q|qp|qf)

// ---- scratch (device globals; no allocations allowed) ----
static __device__ __align__(16) float g_qcat[(size_t)BH*SS*CD];    // [bh][s][192]
static __device__ __align__(16) float g_kcat[(size_t)BH*SS*CD];
static __device__ __align__(16) float g_v[(size_t)BH*SS*DD];       // [bh][s][64]
static __device__ __align__(16) float g_scores[(size_t)BH*SS*SS];  // [bh][q][k]
static __device__ __align__(16) float g_ctx[(size_t)MM*HH];        // [b*s][h*64+d]

struct ProjArgs {
    const float* A[7];
    const float* W[7];
    const float* b[7];
};

// ============================================================
// Kernel 1: 7 fused input projections, 128x128x8 SGEMM (NT),
// scatter epilogue into [bh][s][slot*64+d] layout.
// z: 0=q 1=k 2=v 3=qp 4=kp 5=qf 6=kf
// ============================================================
__global__ void __launch_bounds__(256, 2) proj_kernel(ProjArgs pa) {
    __shared__ __align__(16) float As[2][8][132];
    __shared__ __align__(16) float Bs[2][8][132];

    const int z = blockIdx.z;
    const float* A    = pa.A[z];
    const float* W    = pa.W[z];
    const float* bias = pa.b[z];

    float* outb; int od0; int ldo;
    switch (z) {
        case 0:  outb = g_qcat; od0 = 0;   ldo = CD; break;
        case 1:  outb = g_kcat; od0 = 0;   ldo = CD; break;
        case 2:  outb = g_v;    od0 = 0;   ldo = DD; break;
        case 3:  outb = g_qcat; od0 = 64;  ldo = CD; break;
        case 4:  outb = g_kcat; od0 = 64;  ldo = CD; break;
        case 5:  outb = g_qcat; od0 = 128; ldo = CD; break;
        default: outb = g_kcat; od0 = 128; ldo = CD; break;
    }

    const int tid = threadIdx.x;
    const int tx = tid & 15, ty = tid >> 4;
    const int m0 = blockIdx.y * 128, n0 = blockIdx.x * 128;
    const int lr = tid >> 1, lc = (tid & 1) * 4;

    const float* Ap = A + (size_t)(m0 + lr) * HH + lc;
    const float* Wp = W + (size_t)(n0 + lr) * HH + lc;

    float4 a4 = *(const float4*)Ap;
    float4 b4 = *(const float4*)Wp;
    As[0][lc+0][lr] = a4.x; As[0][lc+1][lr] = a4.y;
    As[0][lc+2][lr] = a4.z; As[0][lc+3][lr] = a4.w;
    Bs[0][lc+0][lr] = b4.x; Bs[0][lc+1][lr] = b4.y;
    Bs[0][lc+2][lr] = b4.z; Bs[0][lc+3][lr] = b4.w;
    __syncthreads();

    float acc[8][8];
    #pragma unroll
    for (int i = 0; i < 8; i++)
        #pragma unroll
        for (int j = 0; j < 8; j++) acc[i][j] = 0.f;

    const int KT = HH / 8;  // 128
    for (int t = 0; t < KT; t++) {
        const int p = t & 1;
        if (t + 1 < KT) {
            a4 = *(const float4*)(Ap + (t + 1) * 8);
            b4 = *(const float4*)(Wp + (t + 1) * 8);
        }
        #pragma unroll
        for (int k = 0; k < 8; k++) {
            float a[8], b[8];
            *(float4*)&a[0] = *(const float4*)&As[p][k][ty*8];
            *(float4*)&a[4] = *(const float4*)&As[p][k][ty*8+4];
            *(float4*)&b[0] = *(const float4*)&Bs[p][k][tx*8];
            *(float4*)&b[4] = *(const float4*)&Bs[p][k][tx*8+4];
            #pragma unroll
            for (int i = 0; i < 8; i++)
                #pragma unroll
                for (int j = 0; j < 8; j++)
                    acc[i][j] += a[i] * b[j];
        }
        if (t + 1 < KT) {
            const int q = (t + 1) & 1;
            As[q][lc+0][lr] = a4.x; As[q][lc+1][lr] = a4.y;
            As[q][lc+2][lr] = a4.z; As[q][lc+3][lr] = a4.w;
            Bs[q][lc+0][lr] = b4.x; Bs[q][lc+1][lr] = b4.y;
            Bs[q][lc+2][lr] = b4.z; Bs[q][lc+3][lr] = b4.w;
            __syncthreads();
        }
    }

    float bv[8];
    #pragma unroll
    for (int j = 0; j < 8; j++) bv[j] = bias[n0 + tx*8 + j];

    #pragma unroll
    for (int i = 0; i < 8; i++) {
        const int m = m0 + ty*8 + i;
        const int b_ = m >> 9, s = m & 511;
        #pragma unroll
        for (int j = 0; j < 8; j++) {
            const int o = n0 + tx*8 + j;
            const int h = o >> 6, d = o & 63;
            outb[(size_t)((b_*NHD + h)*SS + s) * ldo + od0 + d] = acc[i][j] + bv[j];
        }
    }
}

// ============================================================
// Kernel 2: batched scores GEMM [512x512xK=192] per (b,h),
// content snapshot at K=64 -> attention_map output,
// final: scores = acc/8 + mask -> g_scores.
// ============================================================
__global__ void __launch_bounds__(256, 2) scores_kernel(
    const float* __restrict__ mask, float* __restrict__ attnmap) {
    __shared__ __align__(16) float As[2][8][132];
    __shared__ __align__(16) float Bs[2][8][132];

    const int bh = blockIdx.z;
    const int b_ = bh >> 4;
    const float* A  = g_qcat + (size_t)bh * SS * CD;
    const float* Bm = g_kcat + (size_t)bh * SS * CD;

    const int tid = threadIdx.x;
    const int tx = tid & 15, ty = tid >> 4;
    const int m0 = blockIdx.y * 128, n0 = blockIdx.x * 128;
    const int lr = tid >> 1, lc = (tid & 1) * 4;

    const float* Ap = A  + (size_t)(m0 + lr) * CD + lc;
    const float* Bp = Bm + (size_t)(n0 + lr) * CD + lc;

    float4 a4 = *(const float4*)Ap;
    float4 b4 = *(const float4*)Bp;
    As[0][lc+0][lr] = a4.x; As[0][lc+1][lr] = a4.y;
    As[0][lc+2][lr] = a4.z; As[0][lc+3][lr] = a4.w;
    Bs[0][lc+0][lr] = b4.x; Bs[0][lc+1][lr] = b4.y;
    Bs[0][lc+2][lr] = b4.z; Bs[0][lc+3][lr] = b4.w;
    __syncthreads();

    float acc[8][8];
    #pragma unroll
    for (int i = 0; i < 8; i++)
        #pragma unroll
        for (int j = 0; j < 8; j++) acc[i][j] = 0.f;

    const int KT = CD / 8;  // 24; tiles 0..7 are the content (q.k) part
    for (int t = 0; t < KT; t++) {
        const int p = t & 1;
        if (t + 1 < KT) {
            a4 = *(const float4*)(Ap + (t + 1) * 8);
            b4 = *(const float4*)(Bp + (t + 1) * 8);
        }
        #pragma unroll
        for (int k = 0; k < 8; k++) {
            float a[8], b[8];
            *(float4*)&a[0] = *(const float4*)&As[p][k][ty*8];
            *(float4*)&a[4] = *(const float4*)&As[p][k][ty*8+4];
            *(float4*)&b[0] = *(const float4*)&Bs[p][k][tx*8];
            *(float4*)&b[4] = *(const float4*)&Bs[p][k][tx*8+4];
            #pragma unroll
            for (int i = 0; i < 8; i++)
                #pragma unroll
                for (int j = 0; j < 8; j++)
                    acc[i][j] += a[i] * b[j];
        }
        if (t == 7) {  // content part complete -> attention_map
            float* amb = attnmap + (size_t)bh * SS * SS;
            #pragma unroll
            for (int i = 0; i < 8; i++) {
                const int m = m0 + ty*8 + i;
                #pragma unroll
                for (int j = 0; j < 8; j++)
                    amb[(size_t)m * SS + n0 + tx*8 + j] = acc[i][j];
            }
        }
        if (t + 1 < KT) {
            const int q = (t + 1) & 1;
            As[q][lc+0][lr] = a4.x; As[q][lc+1][lr] = a4.y;
            As[q][lc+2][lr] = a4.z; As[q][lc+3][lr] = a4.w;
            Bs[q][lc+0][lr] = b4.x; Bs[q][lc+1][lr] = b4.y;
            Bs[q][lc+2][lr] = b4.z; Bs[q][lc+3][lr] = b4.w;
            __syncthreads();
        }
    }

    float* scb = g_scores + (size_t)bh * SS * SS;
    #pragma unroll
    for (int i = 0; i < 8; i++) {
        const int m = m0 + ty*8 + i;
        const float* mrow = mask + ((size_t)b_ * SS + m) * SS;
        #pragma unroll
        for (int j = 0; j < 8; j++) {
            const int n = n0 + tx*8 + j;
            scb[(size_t)m * SS + n] = acc[i][j] * 0.125f + mrow[n];
        }
    }
}

// ============================================================
// Kernel 3: row softmax, in place on g_scores. 128 thr/row.
// ============================================================
__global__ void softmax_kernel() {
    const size_t r = blockIdx.x;
    float* row = g_scores + r * SS;
    float4 v = ((float4*)row)[threadIdx.x];

    float mx = fmaxf(fmaxf(v.x, v.y), fmaxf(v.z, v.w));
    #pragma unroll
    for (int o = 16; o; o >>= 1) mx = fmaxf(mx, __shfl_xor_sync(0xffffffffu, mx, o));
    __shared__ float sm[4];
    const int w = threadIdx.x >> 5;
    if ((threadIdx.x & 31) == 0) sm[w] = mx;
    __syncthreads();
    mx = fmaxf(fmaxf(sm[0], sm[1]), fmaxf(sm[2], sm[3]));

    v.x = expf(v.x - mx); v.y = expf(v.y - mx);
    v.z = expf(v.z - mx); v.w = expf(v.w - mx);
    float s = v.x + v.y + v.z + v.w;
    #pragma unroll
    for (int o = 16; o; o >>= 1) s += __shfl_xor_sync(0xffffffffu, s, o);
    __shared__ float ss[4];
    if ((threadIdx.x & 31) == 0) ss[w] = s;
    __syncthreads();
    s = ss[0] + ss[1] + ss[2] + ss[3];

    const float inv = 1.f / s;
    v.x *= inv; v.y *= inv; v.z *= inv; v.w *= inv;
    ((float4*)row)[threadIdx.x] = v;
}

// ============================================================
// Kernel 4: ctx = probs @ V per (b,h): [512x512]x[512x64],
// 64x64x16 tiles, write [b][s][h*64+d].
// ============================================================
__global__ void __launch_bounds__(256, 2) ctx_kernel() {
    __shared__ __align__(16) float As[2][16][68];
    __shared__ __align__(16) float Bs[2][16][68];

    const int bh = blockIdx.y;
    const int b_ = bh >> 4, h = bh & 15;
    const float* P = g_scores + (size_t)bh * SS * SS;
    const float* V = g_v      + (size_t)bh * SS * DD;
    const int m0 = blockIdx.x * 64;

    const int tid = threadIdx.x;
    const int tx = tid & 15, ty = tid >> 4;
    const int ar = tid >> 2, ac = (tid & 3) * 4;   // A loader: 64 rows x 16k
    const int br = tid >> 4, bc = (tid & 15) * 4;  // B loader: 16k x 64 cols

    const float* Ap = P + (size_t)(m0 + ar) * SS + ac;
    const float* Vp = V + (size_t)br * DD + bc;

    float4 a4 = *(const float4*)Ap;
    float4 b4 = *(const float4*)Vp;
    As[0][ac+0][ar] = a4.x; As[0][ac+1][ar] = a4.y;
    As[0][ac+2][ar] = a4.z; As[0][ac+3][ar] = a4.w;
    *(float4*)&Bs[0][br][bc] = b4;
    __syncthreads();

    float acc[4][4];
    #pragma unroll
    for (int i = 0; i < 4; i++)
        #pragma unroll
        for (int j = 0; j < 4; j++) acc[i][j] = 0.f;

    const int KT = SS / 16;  // 32
    for (int t = 0; t < KT; t++) {
        const int p = t & 1;
        if (t + 1 < KT) {
            a4 = *(const float4*)(Ap + (t + 1) * 16);
            b4 = *(const float4*)(Vp + (size_t)(t + 1) * 16 * DD);
        }
        #pragma unroll
        for (int k = 0; k < 16; k++) {
            float a[4], b[4];
            *(float4*)&a[0] = *(const float4*)&As[p][k][ty*4];
            *(float4*)&b[0] = *(const float4*)&Bs[p][k][tx*4];
            #pragma unroll
            for (int i = 0; i < 4; i++)
                #pragma unroll
                for (int j = 0; j < 4; j++)
                    acc[i][j] += a[i] * b[j];
        }
        if (t + 1 < KT) {
            const int q = (t + 1) & 1;
            As[q][ac+0][ar] = a4.x; As[q][ac+1][ar] = a4.y;
            As[q][ac+2][ar] = a4.z; As[q][ac+3][ar] = a4.w;
            *(float4*)&Bs[q][br][bc] = b4;
            __syncthreads();
        }
    }

    #pragma unroll
    for (int i = 0; i < 4; i++) {
        const int s = m0 + ty*4 + i;
        #pragma unroll
        for (int j = 0; j < 4; j++) {
            const int d = tx*4 + j;
            g_ctx[(size_t)(b_*SS + s) * HH + h*DD + d] = acc[i][j];
        }
    }
}

// ============================================================
// Kernel 5: hidden = ctx @ Wd^T + bd. 128x128x8 SGEMM, plain out.
// ============================================================
__global__ void __launch_bounds__(256, 2) final_kernel(
    const float* __restrict__ W, const float* __restrict__ bias,
    float* __restrict__ C) {
    __shared__ __align__(16) float As[2][8][132];
    __shared__ __align__(16) float Bs[2][8][132];

    const int tid = threadIdx.x;
    const int tx = tid & 15, ty = tid >> 4;
    const int m0 = blockIdx.y * 128, n0 = blockIdx.x * 128;
    const int lr = tid >> 1, lc = (tid & 1) * 4;

    const float* Ap = g_ctx + (size_t)(m0 + lr) * HH + lc;
    const float* Wp = W     + (size_t)(n0 + lr) * HH + lc;

    float4 a4 = *(const float4*)Ap;
    float4 b4 = *(const float4*)Wp;
    As[0][lc+0][lr] = a4.x; As[0][lc+1][lr] = a4.y;
    As[0][lc+2][lr] = a4.z; As[0][lc+3][lr] = a4.w;
    Bs[0][lc+0][lr] = b4.x; Bs[0][lc+1][lr] = b4.y;
    Bs[0][lc+2][lr] = b4.z; Bs[0][lc+3][lr] = b4.w;
    __syncthreads();

    float acc[8][8];
    #pragma unroll
    for (int i = 0; i < 8; i++)
        #pragma unroll
        for (int j = 0; j < 8; j++) acc[i][j] = 0.f;

    const int KT = HH / 8;
    for (int t = 0; t < KT; t++) {
        const int p = t & 1;
        if (t + 1 < KT) {
            a4 = *(const float4*)(Ap + (t + 1) * 8);
            b4 = *(const float4*)(Wp + (t + 1) * 8);
        }
        #pragma unroll
        for (int k = 0; k < 8; k++) {
            float a[8], b[8];
            *(float4*)&a[0] = *(const float4*)&As[p][k][ty*8];
            *(float4*)&a[4] = *(const float4*)&As[p][k][ty*8+4];
            *(float4*)&b[0] = *(const float4*)&Bs[p][k][tx*8];
            *(float4*)&b[4] = *(const float4*)&Bs[p][k][tx*8+4];
            #pragma unroll
            for (int i = 0; i < 8; i++)
                #pragma unroll
                for (int j = 0; j < 8; j++)
                    acc[i][j] += a[i] * b[j];
        }
        if (t + 1 < KT) {
            const int q = (t + 1) & 1;
            As[q][lc+0][lr] = a4.x; As[q][lc+1][lr] = a4.y;
            As[q][lc+2][lr] = a4.z; As[q][lc+3][lr] = a4.w;
            Bs[q][lc+0][lr] = b4.x; Bs[q][lc+1][lr] = b4.y;
            Bs[q][lc+2][lr] = b4.z; Bs[q][lc+3][lr] = b4.w;
            __syncthreads();
        }
    }

    float bv[8];
    #pragma unroll
    for (int j = 0; j < 8; j++) bv[j] = bias[n0 + tx*8 + j];

    #pragma unroll
    for (int i = 0; i < 8; i++) {
        const int m = m0 + ty*8 + i;
        #pragma unroll
        for (int j = 0; j < 8; j++)
            C[(size_t)m * HH + n0 + tx*8 + j] = acc[i][j] + bv[j];
    }
}

// ============================================================
// Launch
// ============================================================
extern "C" void kernel_launch(void* const* d_in, const int* in_sizes, int n_in,
                              void* d_out, int out_size) {
    (void)in_sizes; (void)n_in; (void)out_size;

    const float* query = (const float*)d_in[0];
    const float* key   = (const float*)d_in[1];
    const float* value = (const float*)d_in[2];
    const float* mask  = (const float*)d_in[3];
    const float* pos   = (const float*)d_in[4];
    const float* feat  = (const float*)d_in[5];

    ProjArgs pa;
    const float* Ains[7] = {query, key, value, pos, pos, feat, feat};
    for (int i = 0; i < 7; i++) {
        pa.A[i] = Ains[i];
        pa.W[i] = (const float*)d_in[6 + 2*i];
        pa.b[i] = (const float*)d_in[7 + 2*i];
    }
    const float* Wd = (const float*)d_in[20];
    const float* bd = (const float*)d_in[21];

    float* out     = (float*)d_out;
    float* hidden  = out;                        // [B,S,H]
    float* attnmap = out + (size_t)MM * HH;      // [B,NH,S,S]

    proj_kernel<<<dim3(8, 32, 7), 256>>>(pa);
    scores_kernel<<<dim3(4, 4, BH), 256>>>(mask, attnmap);
    softmax_kernel<<<BH * SS, 128>>>();
    ctx_kernel<<<dim3(8, BH), 256>>>();
    final_kernel<<<dim3(8, 32), 256>>>(Wd, bd, hidden);
}

// round 3
// speedup vs baseline: 1.8160x; 1.8160x over previous
#include <cuda_runtime.h>
#include <cuda_bf16.h>
#include <math.h>
#include <cstdint>

#define BB 8
#define SS 512
#define HH 1024
#define NHD 16
#define DD 64
#define MM (BB*SS)      // 4096
#define BH (BB*NHD)     // 128
#define CD 192          // concatenated head dim (q|qp|qf)

// ---- scratch (device globals; no allocations allowed) ----
static __device__ __align__(16) float g_v[(size_t)BH*SS*DD];       // [bh][s][64]
static __device__ __align__(16) float g_scores[(size_t)BH*SS*SS];  // [bh][q][k]
static __device__ __align__(16) float g_ctx[(size_t)MM*HH];        // [b*s][h*64+d]

static __device__ __align__(16) __nv_bfloat16 g_qcat_hi[(size_t)BH*SS*CD];
static __device__ __align__(16) __nv_bfloat16 g_qcat_lo[(size_t)BH*SS*CD];
static __device__ __align__(16) __nv_bfloat16 g_kcat_hi[(size_t)BH*SS*CD];
static __device__ __align__(16) __nv_bfloat16 g_kcat_lo[(size_t)BH*SS*CD];
static __device__ __align__(16) __nv_bfloat16 g_act_hi[(size_t)5*MM*HH];
static __device__ __align__(16) __nv_bfloat16 g_act_lo[(size_t)5*MM*HH];
static __device__ __align__(16) __nv_bfloat16 g_w_hi[(size_t)8*HH*HH];
static __device__ __align__(16) __nv_bfloat16 g_w_lo[(size_t)8*HH*HH];
static __device__ __align__(16) __nv_bfloat16 g_ctx_hi[(size_t)MM*HH];
static __device__ __align__(16) __nv_bfloat16 g_ctx_lo[(size_t)MM*HH];

// ---- mma tile geometry ----
// CTA 256 thr = 8 warps (2x4), tile 128x128, K-chunk 32.
// smem per buffer: 4 subtiles (Ah,Al,Bh,Bl), each 128 rows x 40 bf16 (32 used).
#define TILE_B 10240                 // 128*40*2 bytes
#define BUF_B  (4*TILE_B)            // 40960
#define SMEM_B (2*BUF_B)             // 81920

__device__ __forceinline__ uint32_t smem_to_u32(const void* p) {
    uint32_t a;
    asm("{ .reg .u64 t; cvta.to.shared.u64 t, %1; cvt.u32.u64 %0, t; }" : "=r"(a) : "l"(p));
    return a;
}
__device__ __forceinline__ void cp16(uint32_t s, const void* g) {
    asm volatile("cp.async.cg.shared.global [%0], [%1], 16;" :: "r"(s), "l"(g));
}
#define CP_COMMIT() asm volatile("cp.async.commit_group;" ::: "memory")
template<int N> __device__ __forceinline__ void cp_wait() {
    asm volatile("cp.async.wait_group %0;" :: "n"(N) : "memory");
}

__device__ __forceinline__ void mma_bf(float* c, const uint32_t* a, const uint32_t* b) {
    asm volatile(
        "mma.sync.aligned.m16n8k16.row.col.f32.bf16.bf16.f32 "
        "{%0,%1,%2,%3}, {%4,%5,%6,%7}, {%8,%9}, {%0,%1,%2,%3};"
        : "+f"(c[0]), "+f"(c[1]), "+f"(c[2]), "+f"(c[3])
        : "r"(a[0]), "r"(a[1]), "r"(a[2]), "r"(a[3]), "r"(b[0]), "r"(b[1]));
}

// Load one K-chunk (k0..k0+31) of A(hi,lo) rows m0..m0+127 and B(hi,lo) rows
// n0..n0+127 into one smem buffer. 8 cp.async per thread.
__device__ __forceinline__ void load_chunk(uint32_t sbuf, int tid,
    const __nv_bfloat16* __restrict__ Ah, const __nv_bfloat16* __restrict__ Al, int lda,
    const __nv_bfloat16* __restrict__ Bh, const __nv_bfloat16* __restrict__ Bl, int ldb,
    int m0, int n0, int k0) {
    #pragma unroll
    for (int j = 0; j < 2; j++) {
        const int u = tid + 256*j;               // 0..511 uint4 slots
        const int row = u >> 2, cg = (u & 3) * 8;
        const uint32_t so = (uint32_t)(row*40 + cg)*2;
        const size_t ga = (size_t)(m0+row)*lda + k0 + cg;
        const size_t gb = (size_t)(n0+row)*ldb + k0 + cg;
        cp16(sbuf + so,            Ah + ga);
        cp16(sbuf + TILE_B + so,   Al + ga);
        cp16(sbuf + 2*TILE_B + so, Bh + gb);
        cp16(sbuf + 3*TILE_B + so, Bl + gb);
    }
    CP_COMMIT();
}

// One K-chunk of bf16x3 mma: acc += Ah*Bh + Ah*Bl + Al*Bh over k0..k0+31.
__device__ __forceinline__ void mma_chunk(const char* buf, int lane, int wm, int wn,
                                          float acc[4][4][4]) {
    const int r0 = lane >> 2, tig = lane & 3;
    #pragma unroll
    for (int kk = 0; kk < 2; kk++) {
        const int c = kk*16 + tig*2;
        uint32_t ah[4][4], al[4][4];
        #pragma unroll
        for (int mt = 0; mt < 4; mt++) {
            const int r = wm*64 + mt*16 + r0;
            const char* p0 = buf + (r*40 + c)*2;
            const char* p1 = buf + ((r+8)*40 + c)*2;
            ah[mt][0] = *(const uint32_t*)(p0);
            ah[mt][1] = *(const uint32_t*)(p1);
            ah[mt][2] = *(const uint32_t*)(p0 + 16);
            ah[mt][3] = *(const uint32_t*)(p1 + 16);
            al[mt][0] = *(const uint32_t*)(p0 + TILE_B);
            al[mt][1] = *(const uint32_t*)(p1 + TILE_B);
            al[mt][2] = *(const uint32_t*)(p0 + TILE_B + 16);
            al[mt][3] = *(const uint32_t*)(p1 + TILE_B + 16);
        }
        uint32_t bh[4][2], bl[4][2];
        #pragma unroll
        for (int nt = 0; nt < 4; nt++) {
            const int n = wn*32 + nt*8 + r0;
            const char* p = buf + 2*TILE_B + (n*40 + c)*2;
            bh[nt][0] = *(const uint32_t*)(p);
            bh[nt][1] = *(const uint32_t*)(p + 16);
            bl[nt][0] = *(const uint32_t*)(p + TILE_B);
            bl[nt][1] = *(const uint32_t*)(p + TILE_B + 16);
        }
        #pragma unroll
        for (int mt = 0; mt < 4; mt++)
            #pragma unroll
            for (int nt = 0; nt < 4; nt++) {
                mma_bf(acc[mt][nt], ah[mt], bh[nt]);
                mma_bf(acc[mt][nt], ah[mt], bl[nt]);
                mma_bf(acc[mt][nt], al[mt], bh[nt]);
            }
    }
}

// ============================================================
// Kernel 0: convert fp32 -> bf16 hi/lo.
// z 0..4: activations (q,k,v,pos,feat); z 5..12: weights (Wq..Wkf,Wd)
// ============================================================
struct ConvArgs { const float* src[13]; };

__global__ void convert_kernel(ConvArgs ca) {
    const int z = blockIdx.z;
    const size_t nvec = (z < 5) ? (size_t)MM*HH/4 : (size_t)HH*HH/4;
    const size_t i = (size_t)blockIdx.x * 256 + threadIdx.x;
    if (i >= nvec) return;
    const float4 v = ((const float4*)ca.src[z])[i];

    __nv_bfloat16 h0 = __float2bfloat16_rn(v.x);
    __nv_bfloat16 h1 = __float2bfloat16_rn(v.y);
    __nv_bfloat16 h2 = __float2bfloat16_rn(v.z);
    __nv_bfloat16 h3 = __float2bfloat16_rn(v.w);
    __nv_bfloat16 l0 = __float2bfloat16_rn(v.x - __bfloat162float(h0));
    __nv_bfloat16 l1 = __float2bfloat16_rn(v.y - __bfloat162float(h1));
    __nv_bfloat16 l2 = __float2bfloat16_rn(v.z - __bfloat162float(h2));
    __nv_bfloat16 l3 = __float2bfloat16_rn(v.w - __bfloat162float(h3));

    __nv_bfloat16 *dh, *dl;
    if (z < 5) { dh = g_act_hi + (size_t)z*MM*HH + i*4; dl = g_act_lo + (size_t)z*MM*HH + i*4; }
    else       { dh = g_w_hi + (size_t)(z-5)*HH*HH + i*4; dl = g_w_lo + (size_t)(z-5)*HH*HH + i*4; }
    *(ushort4*)dh = make_ushort4(__bfloat16_as_ushort(h0), __bfloat16_as_ushort(h1),
                                 __bfloat16_as_ushort(h2), __bfloat16_as_ushort(h3));
    *(ushort4*)dl = make_ushort4(__bfloat16_as_ushort(l0), __bfloat16_as_ushort(l1),
                                 __bfloat16_as_ushort(l2), __bfloat16_as_ushort(l3));
}

__global__ void convert_ctx_kernel() {
    const size_t i = (size_t)blockIdx.x * 256 + threadIdx.x;   // < MM*HH/4
    const float4 v = ((const float4*)g_ctx)[i];
    __nv_bfloat16 h0 = __float2bfloat16_rn(v.x);
    __nv_bfloat16 h1 = __float2bfloat16_rn(v.y);
    __nv_bfloat16 h2 = __float2bfloat16_rn(v.z);
    __nv_bfloat16 h3 = __float2bfloat16_rn(v.w);
    __nv_bfloat16 l0 = __float2bfloat16_rn(v.x - __bfloat162float(h0));
    __nv_bfloat16 l1 = __float2bfloat16_rn(v.y - __bfloat162float(h1));
    __nv_bfloat16 l2 = __float2bfloat16_rn(v.z - __bfloat162float(h2));
    __nv_bfloat16 l3 = __float2bfloat16_rn(v.w - __bfloat162float(h3));
    *(ushort4*)(g_ctx_hi + i*4) = make_ushort4(__bfloat16_as_ushort(h0), __bfloat16_as_ushort(h1),
                                               __bfloat16_as_ushort(h2), __bfloat16_as_ushort(h3));
    *(ushort4*)(g_ctx_lo + i*4) = make_ushort4(__bfloat16_as_ushort(l0), __bfloat16_as_ushort(l1),
                                               __bfloat16_as_ushort(l2), __bfloat16_as_ushort(l3));
}

// ============================================================
// Kernel 1: 7 fused projections, mma.sync bf16x3, C = A*W^T + b.
// Epilogue scatters into per-head layout: q/qp/qf,k/kp/kf as bf16 hi/lo
// concat tensors; v as fp32.
// ============================================================
struct TCArgs { const float* bias[7]; };

__global__ void proj_mma_kernel(TCArgs ta) {
    extern __shared__ char smem[];
    const int tid = threadIdx.x, lane = tid & 31, w = tid >> 5;
    const int wm = w & 1, wn = w >> 1;
    const int z = blockIdx.z;
    const int ai = (z <= 2) ? z : (z <= 4 ? 3 : 4);
    const int m0 = blockIdx.y * 128, n0 = blockIdx.x * 128;

    const __nv_bfloat16* Ah = g_act_hi + (size_t)ai*MM*HH;
    const __nv_bfloat16* Al = g_act_lo + (size_t)ai*MM*HH;
    const __nv_bfloat16* Bh = g_w_hi + (size_t)z*HH*HH;
    const __nv_bfloat16* Bl = g_w_lo + (size_t)z*HH*HH;
    const uint32_t sb = smem_to_u32(smem);

    float acc[4][4][4];
    #pragma unroll
    for (int a = 0; a < 4; a++)
        #pragma unroll
        for (int b = 0; b < 4; b++)
            #pragma unroll
            for (int c = 0; c < 4; c++) acc[a][b][c] = 0.f;

    load_chunk(sb, tid, Ah, Al, HH, Bh, Bl, HH, m0, n0, 0);
    load_chunk(sb + BUF_B, tid, Ah, Al, HH, Bh, Bl, HH, m0, n0, 32);
    const int KT = HH / 32;  // 32
    for (int t = 0; t < KT; t++) {
        cp_wait<1>();
        __syncthreads();
        mma_chunk(smem + (t & 1)*BUF_B, lane, wm, wn, acc);
        __syncthreads();
        if (t + 2 < KT)
            load_chunk(sb + (t & 1)*BUF_B, tid, Ah, Al, HH, Bh, Bl, HH, m0, n0, (t+2)*32);
        else
            CP_COMMIT();
    }

    int od0 = 0;
    __nv_bfloat16 *dh = nullptr, *dl = nullptr;
    switch (z) {
        case 0: dh = g_qcat_hi; dl = g_qcat_lo; od0 = 0;   break;
        case 1: dh = g_kcat_hi; dl = g_kcat_lo; od0 = 0;   break;
        case 2: break;  // v -> fp32
        case 3: dh = g_qcat_hi; dl = g_qcat_lo; od0 = 64;  break;
        case 4: dh = g_kcat_hi; dl = g_kcat_lo; od0 = 64;  break;
        case 5: dh = g_qcat_hi; dl = g_qcat_lo; od0 = 128; break;
        default: dh = g_kcat_hi; dl = g_kcat_lo; od0 = 128; break;
    }
    const float* bias = ta.bias[z];
    const int r0 = lane >> 2, tig = lane & 3;
    #pragma unroll
    for (int mt = 0; mt < 4; mt++)
        #pragma unroll
        for (int nt = 0; nt < 4; nt++) {
            const int n = n0 + wn*32 + nt*8 + tig*2;
            const float bv0 = bias[n], bv1 = bias[n+1];
            const int h = n >> 6, d = n & 63;
            #pragma unroll
            for (int rr = 0; rr < 2; rr++) {
                const int m = m0 + wm*64 + mt*16 + r0 + rr*8;
                const int b_ = m >> 9, s = m & 511;
                const float v0 = acc[mt][nt][rr*2]   + bv0;
                const float v1 = acc[mt][nt][rr*2+1] + bv1;
                if (z == 2) {
                    float2 t2 = make_float2(v0, v1);
                    *(float2*)&g_v[((size_t)((b_*NHD + h)*SS + s))*DD + d] = t2;
                } else {
                    const size_t idx = ((size_t)((b_*NHD + h)*SS + s))*CD + od0 + d;
                    __nv_bfloat16 h0 = __float2bfloat16_rn(v0);
                    __nv_bfloat16 h1 = __float2bfloat16_rn(v1);
                    __nv_bfloat16 q0 = __float2bfloat16_rn(v0 - __bfloat162float(h0));
                    __nv_bfloat16 q1 = __float2bfloat16_rn(v1 - __bfloat162float(h1));
                    *(uint32_t*)&dh[idx] =
                        ((uint32_t)__bfloat16_as_ushort(h1) << 16) | __bfloat16_as_ushort(h0);
                    *(uint32_t*)&dl[idx] =
                        ((uint32_t)__bfloat16_as_ushort(q1) << 16) | __bfloat16_as_ushort(q0);
                }
            }
        }
}

// ============================================================
// Kernel 2: scores per (b,h): [512x512 x K=192] mma bf16x3,
// snapshot at K=64 -> attention_map; final scores = acc/8 + mask.
// ============================================================
__global__ void scores_mma_kernel(const float* __restrict__ mask,
                                  float* __restrict__ attnmap) {
    extern __shared__ char smem[];
    const int tid = threadIdx.x, lane = tid & 31, w = tid >> 5;
    const int wm = w & 1, wn = w >> 1;
    const int bh = blockIdx.z, b_ = bh >> 4;
    const int m0 = blockIdx.y * 128, n0 = blockIdx.x * 128;

    const __nv_bfloat16* Ah = g_qcat_hi + (size_t)bh*SS*CD;
    const __nv_bfloat16* Al = g_qcat_lo + (size_t)bh*SS*CD;
    const __nv_bfloat16* Bh = g_kcat_hi + (size_t)bh*SS*CD;
    const __nv_bfloat16* Bl = g_kcat_lo + (size_t)bh*SS*CD;
    const uint32_t sb = smem_to_u32(smem);
    const int r0 = lane >> 2, tig = lane & 3;

    float acc[4][4][4];
    #pragma unroll
    for (int a = 0; a < 4; a++)
        #pragma unroll
        for (int b = 0; b < 4; b++)
            #pragma unroll
            for (int c = 0; c < 4; c++) acc[a][b][c] = 0.f;

    load_chunk(sb, tid, Ah, Al, CD, Bh, Bl, CD, m0, n0, 0);
    load_chunk(sb + BUF_B, tid, Ah, Al, CD, Bh, Bl, CD, m0, n0, 32);
    const int KT = CD / 32;  // 6
    for (int t = 0; t < KT; t++) {
        cp_wait<1>();
        __syncthreads();
        mma_chunk(smem + (t & 1)*BUF_B, lane, wm, wn, acc);
        if (t == 1) {  // content part (K=0..63) complete -> attention_map
            float* amb = attnmap + (size_t)bh*SS*SS;
            #pragma unroll
            for (int mt = 0; mt < 4; mt++)
                #pragma unroll
                for (int nt = 0; nt < 4; nt++) {
                    const int n = n0 + wn*32 + nt*8 + tig*2;
                    #pragma unroll
                    for (int rr = 0; rr < 2; rr++) {
                        const int m = m0 + wm*64 + mt*16 + r0 + rr*8;
                        float2 t2 = make_float2(acc[mt][nt][rr*2], acc[mt][nt][rr*2+1]);
                        *(float2*)&amb[(size_t)m*SS + n] = t2;
                    }
                }
        }
        __syncthreads();
        if (t + 2 < KT)
            load_chunk(sb + (t & 1)*BUF_B, tid, Ah, Al, CD, Bh, Bl, CD, m0, n0, (t+2)*32);
        else
            CP_COMMIT();
    }

    float* scb = g_scores + (size_t)bh*SS*SS;
    #pragma unroll
    for (int mt = 0; mt < 4; mt++)
        #pragma unroll
        for (int nt = 0; nt < 4; nt++) {
            const int n = n0 + wn*32 + nt*8 + tig*2;
            #pragma unroll
            for (int rr = 0; rr < 2; rr++) {
                const int m = m0 + wm*64 + mt*16 + r0 + rr*8;
                const float2 mk = *(const float2*)&mask[((size_t)b_*SS + m)*SS + n];
                float2 t2 = make_float2(acc[mt][nt][rr*2]*0.125f + mk.x,
                                        acc[mt][nt][rr*2+1]*0.125f + mk.y);
                *(float2*)&scb[(size_t)m*SS + n] = t2;
            }
        }
}

// ============================================================
// Kernel 5: hidden = ctx @ Wd^T + bd, mma bf16x3.
// ============================================================
__global__ void final_mma_kernel(const float* __restrict__ bias,
                                 float* __restrict__ out) {
    extern __shared__ char smem[];
    const int tid = threadIdx.x, lane = tid & 31, w = tid >> 5;
    const int wm = w & 1, wn = w >> 1;
    const int m0 = blockIdx.y * 128, n0 = blockIdx.x * 128;

    const __nv_bfloat16* Ah = g_ctx_hi;
    const __nv_bfloat16* Al = g_ctx_lo;
    const __nv_bfloat16* Bh = g_w_hi + (size_t)7*HH*HH;
    const __nv_bfloat16* Bl = g_w_lo + (size_t)7*HH*HH;
    const uint32_t sb = smem_to_u32(smem);

    float acc[4][4][4];
    #pragma unroll
    for (int a = 0; a < 4; a++)
        #pragma unroll
        for (int b = 0; b < 4; b++)
            #pragma unroll
            for (int c = 0; c < 4; c++) acc[a][b][c] = 0.f;

    load_chunk(sb, tid, Ah, Al, HH, Bh, Bl, HH, m0, n0, 0);
    load_chunk(sb + BUF_B, tid, Ah, Al, HH, Bh, Bl, HH, m0, n0, 32);
    const int KT = HH / 32;
    for (int t = 0; t < KT; t++) {
        cp_wait<1>();
        __syncthreads();
        mma_chunk(smem + (t & 1)*BUF_B, lane, wm, wn, acc);
        __syncthreads();
        if (t + 2 < KT)
            load_chunk(sb + (t & 1)*BUF_B, tid, Ah, Al, HH, Bh, Bl, HH, m0, n0, (t+2)*32);
        else
            CP_COMMIT();
    }

    const int r0 = lane >> 2, tig = lane & 3;
    #pragma unroll
    for (int mt = 0; mt < 4; mt++)
        #pragma unroll
        for (int nt = 0; nt < 4; nt++) {
            const int n = n0 + wn*32 + nt*8 + tig*2;
            const float bv0 = bias[n], bv1 = bias[n+1];
            #pragma unroll
            for (int rr = 0; rr < 2; rr++) {
                const int m = m0 + wm*64 + mt*16 + r0 + rr*8;
                float2 t2 = make_float2(acc[mt][nt][rr*2] + bv0,
                                        acc[mt][nt][rr*2+1] + bv1);
                *(float2*)&out[(size_t)m*HH + n] = t2;
            }
        }
}

// ============================================================
// Kernel 3: row softmax, in place on g_scores.
// ============================================================
__global__ void softmax_kernel() {
    const size_t r = blockIdx.x;
    float* row = g_scores + r * SS;
    float4 v = ((float4*)row)[threadIdx.x];

    float mx = fmaxf(fmaxf(v.x, v.y), fmaxf(v.z, v.w));
    #pragma unroll
    for (int o = 16; o; o >>= 1) mx = fmaxf(mx, __shfl_xor_sync(0xffffffffu, mx, o));
    __shared__ float sm[4];
    const int w = threadIdx.x >> 5;
    if ((threadIdx.x & 31) == 0) sm[w] = mx;
    __syncthreads();
    mx = fmaxf(fmaxf(sm[0], sm[1]), fmaxf(sm[2], sm[3]));

    v.x = expf(v.x - mx); v.y = expf(v.y - mx);
    v.z = expf(v.z - mx); v.w = expf(v.w - mx);
    float s = v.x + v.y + v.z + v.w;
    #pragma unroll
    for (int o = 16; o; o >>= 1) s += __shfl_xor_sync(0xffffffffu, s, o);
    __shared__ float ss[4];
    if ((threadIdx.x & 31) == 0) ss[w] = s;
    __syncthreads();
    s = ss[0] + ss[1] + ss[2] + ss[3];

    const float inv = 1.f / s;
    v.x *= inv; v.y *= inv; v.z *= inv; v.w *= inv;
    ((float4*)row)[threadIdx.x] = v;
}

// ============================================================
// Kernel 4: ctx = probs @ V per (b,h), fp32 SIMT.
// ============================================================
__global__ void __launch_bounds__(256, 2) ctx_kernel() {
    __shared__ __align__(16) float As[2][16][68];
    __shared__ __align__(16) float Bs[2][16][68];

    const int bh = blockIdx.y;
    const int b_ = bh >> 4, h = bh & 15;
    const float* P = g_scores + (size_t)bh * SS * SS;
    const float* V = g_v      + (size_t)bh * SS * DD;
    const int m0 = blockIdx.x * 64;

    const int tid = threadIdx.x;
    const int tx = tid & 15, ty = tid >> 4;
    const int ar = tid >> 2, ac = (tid & 3) * 4;
    const int br = tid >> 4, bc = (tid & 15) * 4;

    const float* Ap = P + (size_t)(m0 + ar) * SS + ac;
    const float* Vp = V + (size_t)br * DD + bc;

    float4 a4 = *(const float4*)Ap;
    float4 b4 = *(const float4*)Vp;
    As[0][ac+0][ar] = a4.x; As[0][ac+1][ar] = a4.y;
    As[0][ac+2][ar] = a4.z; As[0][ac+3][ar] = a4.w;
    *(float4*)&Bs[0][br][bc] = b4;
    __syncthreads();

    float acc[4][4];
    #pragma unroll
    for (int i = 0; i < 4; i++)
        #pragma unroll
        for (int j = 0; j < 4; j++) acc[i][j] = 0.f;

    const int KT = SS / 16;  // 32
    for (int t = 0; t < KT; t++) {
        const int p = t & 1;
        if (t + 1 < KT) {
            a4 = *(const float4*)(Ap + (t + 1) * 16);
            b4 = *(const float4*)(Vp + (size_t)(t + 1) * 16 * DD);
        }
        #pragma unroll
        for (int k = 0; k < 16; k++) {
            float a[4], b[4];
            *(float4*)&a[0] = *(const float4*)&As[p][k][ty*4];
            *(float4*)&b[0] = *(const float4*)&Bs[p][k][tx*4];
            #pragma unroll
            for (int i = 0; i < 4; i++)
                #pragma unroll
                for (int j = 0; j < 4; j++)
                    acc[i][j] += a[i] * b[j];
        }
        if (t + 1 < KT) {
            const int q = (t + 1) & 1;
            As[q][ac+0][ar] = a4.x; As[q][ac+1][ar] = a4.y;
            As[q][ac+2][ar] = a4.z; As[q][ac+3][ar] = a4.w;
            *(float4*)&Bs[q][br][bc] = b4;
            __syncthreads();
        }
    }

    #pragma unroll
    for (int i = 0; i < 4; i++) {
        const int s = m0 + ty*4 + i;
        #pragma unroll
        for (int j = 0; j < 4; j++) {
            const int d = tx*4 + j;
            g_ctx[(size_t)(b_*SS + s) * HH + h*DD + d] = acc[i][j];
        }
    }
}

// ============================================================
// Launch
// ============================================================
extern "C" void kernel_launch(void* const* d_in, const int* in_sizes, int n_in,
                              void* d_out, int out_size) {
    (void)in_sizes; (void)n_in; (void)out_size;

    const float* query = (const float*)d_in[0];
    const float* key   = (const float*)d_in[1];
    const float* value = (const float*)d_in[2];
    const float* mask  = (const float*)d_in[3];
    const float* pos   = (const float*)d_in[4];
    const float* feat  = (const float*)d_in[5];

    ConvArgs ca;
    ca.src[0] = query; ca.src[1] = key; ca.src[2] = value;
    ca.src[3] = pos;   ca.src[4] = feat;
    for (int i = 0; i < 7; i++) ca.src[5 + i] = (const float*)d_in[6 + 2*i];
    ca.src[12] = (const float*)d_in[20];  // Wd

    TCArgs ta;
    for (int i = 0; i < 7; i++) ta.bias[i] = (const float*)d_in[7 + 2*i];
    const float* bd = (const float*)d_in[21];

    float* out     = (float*)d_out;
    float* hidden  = out;                        // [B,S,H]
    float* attnmap = out + (size_t)MM * HH;      // [B,NH,S,S]

    cudaFuncSetAttribute(proj_mma_kernel,   cudaFuncAttributeMaxDynamicSharedMemorySize, SMEM_B);
    cudaFuncSetAttribute(scores_mma_kernel, cudaFuncAttributeMaxDynamicSharedMemorySize, SMEM_B);
    cudaFuncSetAttribute(final_mma_kernel,  cudaFuncAttributeMaxDynamicSharedMemorySize, SMEM_B);

    convert_kernel<<<dim3(4096, 1, 13), 256>>>(ca);
    proj_mma_kernel<<<dim3(8, 32, 7), 256, SMEM_B>>>(ta);
    scores_mma_kernel<<<dim3(4, 4, BH), 256, SMEM_B>>>(mask, attnmap);
    softmax_kernel<<<BH * SS, 128>>>();
    ctx_kernel<<<dim3(8, BH), 256>>>();
    convert_ctx_kernel<<<4096, 256>>>();
    final_mma_kernel<<<dim3(8, 32), 256, SMEM_B>>>(bd, hidden);
}

// round 4
// speedup vs baseline: 1.8883x; 1.0398x over previous
#include <cuda_runtime.h>
#include <cuda_bf16.h>
#include <math.h>
#include <cstdint>

#define BB 8
#define SS 512
#define HH 1024
#define NHD 16
#define DD 64
#define MM (BB*SS)      // 4096
#define BH (BB*NHD)     // 128
#define CD 192          // concatenated head dim (q|qp|qf)

// ---- scratch (device globals; no allocations allowed) ----
static __device__ __align__(16) float g_v[(size_t)BH*SS*DD];       // [bh][s][64] fp32
static __device__ __align__(16) float g_scores[(size_t)BH*SS*SS];  // [bh][q][k] fp32

static __device__ __align__(16) __nv_bfloat16 g_qcat_hi[(size_t)BH*SS*CD];
static __device__ __align__(16) __nv_bfloat16 g_qcat_lo[(size_t)BH*SS*CD];
static __device__ __align__(16) __nv_bfloat16 g_kcat_hi[(size_t)BH*SS*CD];
static __device__ __align__(16) __nv_bfloat16 g_kcat_lo[(size_t)BH*SS*CD];
static __device__ __align__(16) __nv_bfloat16 g_act_hi[(size_t)5*MM*HH];
static __device__ __align__(16) __nv_bfloat16 g_act_lo[(size_t)5*MM*HH];
static __device__ __align__(16) __nv_bfloat16 g_w_hi[(size_t)8*HH*HH];
static __device__ __align__(16) __nv_bfloat16 g_w_lo[(size_t)8*HH*HH];
static __device__ __align__(16) __nv_bfloat16 g_ctx_hi[(size_t)MM*HH];
static __device__ __align__(16) __nv_bfloat16 g_ctx_lo[(size_t)MM*HH];
static __device__ __align__(16) __nv_bfloat16 g_p_hi[(size_t)BH*SS*SS];   // probs hi
static __device__ __align__(16) __nv_bfloat16 g_p_lo[(size_t)BH*SS*SS];   // probs lo
static __device__ __align__(16) __nv_bfloat16 g_vT_hi[(size_t)BH*DD*SS];  // [bh][d][s]
static __device__ __align__(16) __nv_bfloat16 g_vT_lo[(size_t)BH*DD*SS];

// ---- mma tile geometry (128x128 kernels) ----
#define TILE_B 10240                 // 128*40*2 bytes
#define BUF_B  (4*TILE_B)            // 40960
#define SMEM_B (2*BUF_B)             // 81920

// ---- ctx tile geometry (128x64, A=P[128x32k], B=vT[64x32k]) ----
#define CTILE_A 10240                // 128*40*2
#define CTILE_B 5120                 // 64*40*2
#define CBUF_B  (2*CTILE_A + 2*CTILE_B)  // 30720
#define CSMEM_B (2*CBUF_B)               // 61440

__device__ __forceinline__ uint32_t smem_to_u32(const void* p) {
    uint32_t a;
    asm("{ .reg .u64 t; cvta.to.shared.u64 t, %1; cvt.u32.u64 %0, t; }" : "=r"(a) : "l"(p));
    return a;
}
__device__ __forceinline__ void cp16(uint32_t s, const void* g) {
    asm volatile("cp.async.cg.shared.global [%0], [%1], 16;" :: "r"(s), "l"(g));
}
#define CP_COMMIT() asm volatile("cp.async.commit_group;" ::: "memory")
template<int N> __device__ __forceinline__ void cp_wait() {
    asm volatile("cp.async.wait_group %0;" :: "n"(N) : "memory");
}

__device__ __forceinline__ void mma_bf(float* c, const uint32_t* a, const uint32_t* b) {
    asm volatile(
        "mma.sync.aligned.m16n8k16.row.col.f32.bf16.bf16.f32 "
        "{%0,%1,%2,%3}, {%4,%5,%6,%7}, {%8,%9}, {%0,%1,%2,%3};"
        : "+f"(c[0]), "+f"(c[1]), "+f"(c[2]), "+f"(c[3])
        : "r"(a[0]), "r"(a[1]), "r"(a[2]), "r"(a[3]), "r"(b[0]), "r"(b[1]));
}

// Load one K-chunk of A(hi,lo) 128 rows and B(hi,lo) 128 rows into one buffer.
__device__ __forceinline__ void load_chunk(uint32_t sbuf, int tid,
    const __nv_bfloat16* __restrict__ Ah, const __nv_bfloat16* __restrict__ Al, int lda,
    const __nv_bfloat16* __restrict__ Bh, const __nv_bfloat16* __restrict__ Bl, int ldb,
    int m0, int n0, int k0) {
    #pragma unroll
    for (int j = 0; j < 2; j++) {
        const int u = tid + 256*j;               // 0..511 uint4 slots
        const int row = u >> 2, cg = (u & 3) * 8;
        const uint32_t so = (uint32_t)(row*40 + cg)*2;
        const size_t ga = (size_t)(m0+row)*lda + k0 + cg;
        const size_t gb = (size_t)(n0+row)*ldb + k0 + cg;
        cp16(sbuf + so,            Ah + ga);
        cp16(sbuf + TILE_B + so,   Al + ga);
        cp16(sbuf + 2*TILE_B + so, Bh + gb);
        cp16(sbuf + 3*TILE_B + so, Bl + gb);
    }
    CP_COMMIT();
}

// One K-chunk of bf16x3 mma, TERM-MAJOR: within each term all 16 (mt,nt)
// mmas hit distinct accumulators -> no RAW chains on the tensor pipe.
__device__ __forceinline__ void mma_chunk(const char* buf, int lane, int wm, int wn,
                                          float acc[4][4][4]) {
    const int r0 = lane >> 2, tig = lane & 3;
    #pragma unroll
    for (int kk = 0; kk < 2; kk++) {
        const int c = kk*16 + tig*2;
        uint32_t ah[4][4], al[4][4];
        #pragma unroll
        for (int mt = 0; mt < 4; mt++) {
            const int r = wm*64 + mt*16 + r0;
            const char* p0 = buf + (r*40 + c)*2;
            const char* p1 = buf + ((r+8)*40 + c)*2;
            ah[mt][0] = *(const uint32_t*)(p0);
            ah[mt][1] = *(const uint32_t*)(p1);
            ah[mt][2] = *(const uint32_t*)(p0 + 16);
            ah[mt][3] = *(const uint32_t*)(p1 + 16);
            al[mt][0] = *(const uint32_t*)(p0 + TILE_B);
            al[mt][1] = *(const uint32_t*)(p1 + TILE_B);
            al[mt][2] = *(const uint32_t*)(p0 + TILE_B + 16);
            al[mt][3] = *(const uint32_t*)(p1 + TILE_B + 16);
        }
        uint32_t bh[4][2], bl[4][2];
        #pragma unroll
        for (int nt = 0; nt < 4; nt++) {
            const int n = wn*32 + nt*8 + r0;
            const char* p = buf + 2*TILE_B + (n*40 + c)*2;
            bh[nt][0] = *(const uint32_t*)(p);
            bh[nt][1] = *(const uint32_t*)(p + 16);
            bl[nt][0] = *(const uint32_t*)(p + TILE_B);
            bl[nt][1] = *(const uint32_t*)(p + TILE_B + 16);
        }
        #pragma unroll
        for (int mt = 0; mt < 4; mt++)
            #pragma unroll
            for (int nt = 0; nt < 4; nt++)
                mma_bf(acc[mt][nt], ah[mt], bh[nt]);
        #pragma unroll
        for (int mt = 0; mt < 4; mt++)
            #pragma unroll
            for (int nt = 0; nt < 4; nt++)
                mma_bf(acc[mt][nt], ah[mt], bl[nt]);
        #pragma unroll
        for (int mt = 0; mt < 4; mt++)
            #pragma unroll
            for (int nt = 0; nt < 4; nt++)
                mma_bf(acc[mt][nt], al[mt], bh[nt]);
    }
}

// ============================================================
// Kernel 0: convert fp32 -> bf16 hi/lo.
// z 0..4: activations (q,k,v,pos,feat); z 5..12: weights (Wq..Wkf,Wd)
// ============================================================
struct ConvArgs { const float* src[13]; };

__global__ void convert_kernel(ConvArgs ca) {
    const int z = blockIdx.z;
    const size_t nvec = (z < 5) ? (size_t)MM*HH/4 : (size_t)HH*HH/4;
    const size_t i = (size_t)blockIdx.x * 256 + threadIdx.x;
    if (i >= nvec) return;
    const float4 v = ((const float4*)ca.src[z])[i];

    __nv_bfloat16 h0 = __float2bfloat16_rn(v.x);
    __nv_bfloat16 h1 = __float2bfloat16_rn(v.y);
    __nv_bfloat16 h2 = __float2bfloat16_rn(v.z);
    __nv_bfloat16 h3 = __float2bfloat16_rn(v.w);
    __nv_bfloat16 l0 = __float2bfloat16_rn(v.x - __bfloat162float(h0));
    __nv_bfloat16 l1 = __float2bfloat16_rn(v.y - __bfloat162float(h1));
    __nv_bfloat16 l2 = __float2bfloat16_rn(v.z - __bfloat162float(h2));
    __nv_bfloat16 l3 = __float2bfloat16_rn(v.w - __bfloat162float(h3));

    __nv_bfloat16 *dh, *dl;
    if (z < 5) { dh = g_act_hi + (size_t)z*MM*HH + i*4; dl = g_act_lo + (size_t)z*MM*HH + i*4; }
    else       { dh = g_w_hi + (size_t)(z-5)*HH*HH + i*4; dl = g_w_lo + (size_t)(z-5)*HH*HH + i*4; }
    *(ushort4*)dh = make_ushort4(__bfloat16_as_ushort(h0), __bfloat16_as_ushort(h1),
                                 __bfloat16_as_ushort(h2), __bfloat16_as_ushort(h3));
    *(ushort4*)dl = make_ushort4(__bfloat16_as_ushort(l0), __bfloat16_as_ushort(l1),
                                 __bfloat16_as_ushort(l2), __bfloat16_as_ushort(l3));
}

// ============================================================
// Kernel 1: 7 fused projections, mma.sync bf16x3, C = A*W^T + b.
// ============================================================
struct TCArgs { const float* bias[7]; };

__global__ void __launch_bounds__(256, 1) proj_mma_kernel(TCArgs ta) {
    extern __shared__ char smem[];
    const int tid = threadIdx.x, lane = tid & 31, w = tid >> 5;
    const int wm = w & 1, wn = w >> 1;
    const int z = blockIdx.z;
    const int ai = (z <= 2) ? z : (z <= 4 ? 3 : 4);
    const int m0 = blockIdx.y * 128, n0 = blockIdx.x * 128;

    const __nv_bfloat16* Ah = g_act_hi + (size_t)ai*MM*HH;
    const __nv_bfloat16* Al = g_act_lo + (size_t)ai*MM*HH;
    const __nv_bfloat16* Bh = g_w_hi + (size_t)z*HH*HH;
    const __nv_bfloat16* Bl = g_w_lo + (size_t)z*HH*HH;
    const uint32_t sb = smem_to_u32(smem);

    float acc[4][4][4];
    #pragma unroll
    for (int a = 0; a < 4; a++)
        #pragma unroll
        for (int b = 0; b < 4; b++)
            #pragma unroll
            for (int c = 0; c < 4; c++) acc[a][b][c] = 0.f;

    load_chunk(sb, tid, Ah, Al, HH, Bh, Bl, HH, m0, n0, 0);
    load_chunk(sb + BUF_B, tid, Ah, Al, HH, Bh, Bl, HH, m0, n0, 32);
    const int KT = HH / 32;  // 32
    for (int t = 0; t < KT; t++) {
        cp_wait<1>();
        __syncthreads();
        mma_chunk(smem + (t & 1)*BUF_B, lane, wm, wn, acc);
        __syncthreads();
        if (t + 2 < KT)
            load_chunk(sb + (t & 1)*BUF_B, tid, Ah, Al, HH, Bh, Bl, HH, m0, n0, (t+2)*32);
        else
            CP_COMMIT();
    }

    int od0 = 0;
    __nv_bfloat16 *dh = nullptr, *dl = nullptr;
    switch (z) {
        case 0: dh = g_qcat_hi; dl = g_qcat_lo; od0 = 0;   break;
        case 1: dh = g_kcat_hi; dl = g_kcat_lo; od0 = 0;   break;
        case 2: break;  // v -> fp32
        case 3: dh = g_qcat_hi; dl = g_qcat_lo; od0 = 64;  break;
        case 4: dh = g_kcat_hi; dl = g_kcat_lo; od0 = 64;  break;
        case 5: dh = g_qcat_hi; dl = g_qcat_lo; od0 = 128; break;
        default: dh = g_kcat_hi; dl = g_kcat_lo; od0 = 128; break;
    }
    const float* bias = ta.bias[z];
    const int r0 = lane >> 2, tig = lane & 3;
    #pragma unroll
    for (int mt = 0; mt < 4; mt++)
        #pragma unroll
        for (int nt = 0; nt < 4; nt++) {
            const int n = n0 + wn*32 + nt*8 + tig*2;
            const float bv0 = bias[n], bv1 = bias[n+1];
            const int h = n >> 6, d = n & 63;
            #pragma unroll
            for (int rr = 0; rr < 2; rr++) {
                const int m = m0 + wm*64 + mt*16 + r0 + rr*8;
                const int b_ = m >> 9, s = m & 511;
                const float v0 = acc[mt][nt][rr*2]   + bv0;
                const float v1 = acc[mt][nt][rr*2+1] + bv1;
                if (z == 2) {
                    float2 t2 = make_float2(v0, v1);
                    *(float2*)&g_v[((size_t)((b_*NHD + h)*SS + s))*DD + d] = t2;
                } else {
                    const size_t idx = ((size_t)((b_*NHD + h)*SS + s))*CD + od0 + d;
                    __nv_bfloat16 h0 = __float2bfloat16_rn(v0);
                    __nv_bfloat16 h1 = __float2bfloat16_rn(v1);
                    __nv_bfloat16 q0 = __float2bfloat16_rn(v0 - __bfloat162float(h0));
                    __nv_bfloat16 q1 = __float2bfloat16_rn(v1 - __bfloat162float(h1));
                    *(uint32_t*)&dh[idx] =
                        ((uint32_t)__bfloat16_as_ushort(h1) << 16) | __bfloat16_as_ushort(h0);
                    *(uint32_t*)&dl[idx] =
                        ((uint32_t)__bfloat16_as_ushort(q1) << 16) | __bfloat16_as_ushort(q0);
                }
            }
        }
}

// ============================================================
// Kernel 1b: V transpose + hi/lo convert: g_v [bh][s][d] fp32
//            -> g_vT_{hi,lo} [bh][d][s] bf16.
// ============================================================
__global__ void vt_kernel() {
    __shared__ float t[32][33];
    const int bh = blockIdx.z;
    const int s0 = blockIdx.x * 32, d0 = blockIdx.y * 32;
    const int tx = threadIdx.x, ty = threadIdx.y;
    const float* src = g_v + (size_t)bh*SS*DD;
    #pragma unroll
    for (int i = 0; i < 4; i++)
        t[ty + i*8][tx] = src[(size_t)(s0 + ty + i*8)*DD + d0 + tx];
    __syncthreads();
    #pragma unroll
    for (int i = 0; i < 4; i++) {
        const int d = d0 + ty + i*8, s = s0 + tx;
        const float v = t[tx][ty + i*8];
        const __nv_bfloat16 h = __float2bfloat16_rn(v);
        const __nv_bfloat16 l = __float2bfloat16_rn(v - __bfloat162float(h));
        g_vT_hi[(size_t)(bh*DD + d)*SS + s] = h;
        g_vT_lo[(size_t)(bh*DD + d)*SS + s] = l;
    }
}

// ============================================================
// Kernel 2: scores per (b,h): [512x512 x K=192] mma bf16x3,
// snapshot at K=64 -> attention_map; final scores = acc/8 + mask.
// ============================================================
__global__ void __launch_bounds__(256, 1) scores_mma_kernel(
    const float* __restrict__ mask, float* __restrict__ attnmap) {
    extern __shared__ char smem[];
    const int tid = threadIdx.x, lane = tid & 31, w = tid >> 5;
    const int wm = w & 1, wn = w >> 1;
    const int bh = blockIdx.z, b_ = bh >> 4;
    const int m0 = blockIdx.y * 128, n0 = blockIdx.x * 128;

    const __nv_bfloat16* Ah = g_qcat_hi + (size_t)bh*SS*CD;
    const __nv_bfloat16* Al = g_qcat_lo + (size_t)bh*SS*CD;
    const __nv_bfloat16* Bh = g_kcat_hi + (size_t)bh*SS*CD;
    const __nv_bfloat16* Bl = g_kcat_lo + (size_t)bh*SS*CD;
    const uint32_t sb = smem_to_u32(smem);
    const int r0 = lane >> 2, tig = lane & 3;

    float acc[4][4][4];
    #pragma unroll
    for (int a = 0; a < 4; a++)
        #pragma unroll
        for (int b = 0; b < 4; b++)
            #pragma unroll
            for (int c = 0; c < 4; c++) acc[a][b][c] = 0.f;

    load_chunk(sb, tid, Ah, Al, CD, Bh, Bl, CD, m0, n0, 0);
    load_chunk(sb + BUF_B, tid, Ah, Al, CD, Bh, Bl, CD, m0, n0, 32);
    const int KT = CD / 32;  // 6
    for (int t = 0; t < KT; t++) {
        cp_wait<1>();
        __syncthreads();
        mma_chunk(smem + (t & 1)*BUF_B, lane, wm, wn, acc);
        if (t == 1) {  // content part (K=0..63) complete -> attention_map
            float* amb = attnmap + (size_t)bh*SS*SS;
            #pragma unroll
            for (int mt = 0; mt < 4; mt++)
                #pragma unroll
                for (int nt = 0; nt < 4; nt++) {
                    const int n = n0 + wn*32 + nt*8 + tig*2;
                    #pragma unroll
                    for (int rr = 0; rr < 2; rr++) {
                        const int m = m0 + wm*64 + mt*16 + r0 + rr*8;
                        float2 t2 = make_float2(acc[mt][nt][rr*2], acc[mt][nt][rr*2+1]);
                        *(float2*)&amb[(size_t)m*SS + n] = t2;
                    }
                }
        }
        __syncthreads();
        if (t + 2 < KT)
            load_chunk(sb + (t & 1)*BUF_B, tid, Ah, Al, CD, Bh, Bl, CD, m0, n0, (t+2)*32);
        else
            CP_COMMIT();
    }

    float* scb = g_scores + (size_t)bh*SS*SS;
    #pragma unroll
    for (int mt = 0; mt < 4; mt++)
        #pragma unroll
        for (int nt = 0; nt < 4; nt++) {
            const int n = n0 + wn*32 + nt*8 + tig*2;
            #pragma unroll
            for (int rr = 0; rr < 2; rr++) {
                const int m = m0 + wm*64 + mt*16 + r0 + rr*8;
                const float2 mk = *(const float2*)&mask[((size_t)b_*SS + m)*SS + n];
                float2 t2 = make_float2(acc[mt][nt][rr*2]*0.125f + mk.x,
                                        acc[mt][nt][rr*2+1]*0.125f + mk.y);
                *(float2*)&scb[(size_t)m*SS + n] = t2;
            }
        }
}

// ============================================================
// Kernel 3: row softmax on g_scores -> g_p_{hi,lo} bf16.
// ============================================================
__global__ void softmax_kernel() {
    const size_t r = blockIdx.x;
    const float* row = g_scores + r * SS;
    float4 v = ((const float4*)row)[threadIdx.x];

    float mx = fmaxf(fmaxf(v.x, v.y), fmaxf(v.z, v.w));
    #pragma unroll
    for (int o = 16; o; o >>= 1) mx = fmaxf(mx, __shfl_xor_sync(0xffffffffu, mx, o));
    __shared__ float sm[4];
    const int w = threadIdx.x >> 5;
    if ((threadIdx.x & 31) == 0) sm[w] = mx;
    __syncthreads();
    mx = fmaxf(fmaxf(sm[0], sm[1]), fmaxf(sm[2], sm[3]));

    v.x = expf(v.x - mx); v.y = expf(v.y - mx);
    v.z = expf(v.z - mx); v.w = expf(v.w - mx);
    float s = v.x + v.y + v.z + v.w;
    #pragma unroll
    for (int o = 16; o; o >>= 1) s += __shfl_xor_sync(0xffffffffu, s, o);
    __shared__ float ss[4];
    if ((threadIdx.x & 31) == 0) ss[w] = s;
    __syncthreads();
    s = ss[0] + ss[1] + ss[2] + ss[3];

    const float inv = 1.f / s;
    v.x *= inv; v.y *= inv; v.z *= inv; v.w *= inv;

    const __nv_bfloat16 h0 = __float2bfloat16_rn(v.x);
    const __nv_bfloat16 h1 = __float2bfloat16_rn(v.y);
    const __nv_bfloat16 h2 = __float2bfloat16_rn(v.z);
    const __nv_bfloat16 h3 = __float2bfloat16_rn(v.w);
    const __nv_bfloat16 l0 = __float2bfloat16_rn(v.x - __bfloat162float(h0));
    const __nv_bfloat16 l1 = __float2bfloat16_rn(v.y - __bfloat162float(h1));
    const __nv_bfloat16 l2 = __float2bfloat16_rn(v.z - __bfloat162float(h2));
    const __nv_bfloat16 l3 = __float2bfloat16_rn(v.w - __bfloat162float(h3));
    ((ushort4*)(g_p_hi + r*SS))[threadIdx.x] =
        make_ushort4(__bfloat16_as_ushort(h0), __bfloat16_as_ushort(h1),
                     __bfloat16_as_ushort(h2), __bfloat16_as_ushort(h3));
    ((ushort4*)(g_p_lo + r*SS))[threadIdx.x] =
        make_ushort4(__bfloat16_as_ushort(l0), __bfloat16_as_ushort(l1),
                     __bfloat16_as_ushort(l2), __bfloat16_as_ushort(l3));
}

// ============================================================
// Kernel 4: ctx = P @ V via mma bf16x3. Per (bh): A=P[512x512],
// B=vT[64x512]. Tile 128x64, K-chunk 32. Writes ctx hi/lo bf16.
// ============================================================
__device__ __forceinline__ void ctx_load_chunk(uint32_t sbuf, int tid,
    const __nv_bfloat16* __restrict__ Ph, const __nv_bfloat16* __restrict__ Pl,
    const __nv_bfloat16* __restrict__ Vh, const __nv_bfloat16* __restrict__ Vl,
    int m0, int k0) {
    #pragma unroll
    for (int j = 0; j < 2; j++) {
        const int u = tid + 256*j;               // 0..511
        const int row = u >> 2, cg = (u & 3) * 8;
        const uint32_t so = (uint32_t)(row*40 + cg)*2;
        const size_t ga = (size_t)(m0+row)*SS + k0 + cg;
        cp16(sbuf + so,           Ph + ga);
        cp16(sbuf + CTILE_A + so, Pl + ga);
    }
    {
        const int u = tid;                        // 0..255
        const int row = u >> 2, cg = (u & 3) * 8;
        const uint32_t so = (uint32_t)(row*40 + cg)*2;
        const size_t gb = (size_t)row*SS + k0 + cg;
        cp16(sbuf + 2*CTILE_A + so,           Vh + gb);
        cp16(sbuf + 2*CTILE_A + CTILE_B + so, Vl + gb);
    }
    CP_COMMIT();
}

__device__ __forceinline__ void ctx_mma_chunk(const char* buf, int lane, int wm, int wn,
                                              float acc[4][2][4]) {
    const int r0 = lane >> 2, tig = lane & 3;
    #pragma unroll
    for (int kk = 0; kk < 2; kk++) {
        const int c = kk*16 + tig*2;
        uint32_t ah[4][4], al[4][4];
        #pragma unroll
        for (int mt = 0; mt < 4; mt++) {
            const int r = wm*64 + mt*16 + r0;
            const char* p0 = buf + (r*40 + c)*2;
            const char* p1 = buf + ((r+8)*40 + c)*2;
            ah[mt][0] = *(const uint32_t*)(p0);
            ah[mt][1] = *(const uint32_t*)(p1);
            ah[mt][2] = *(const uint32_t*)(p0 + 16);
            ah[mt][3] = *(const uint32_t*)(p1 + 16);
            al[mt][0] = *(const uint32_t*)(p0 + CTILE_A);
            al[mt][1] = *(const uint32_t*)(p1 + CTILE_A);
            al[mt][2] = *(const uint32_t*)(p0 + CTILE_A + 16);
            al[mt][3] = *(const uint32_t*)(p1 + CTILE_A + 16);
        }
        uint32_t bh[2][2], bl[2][2];
        #pragma unroll
        for (int nt = 0; nt < 2; nt++) {
            const int n = wn*16 + nt*8 + r0;
            const char* p = buf + 2*CTILE_A + (n*40 + c)*2;
            bh[nt][0] = *(const uint32_t*)(p);
            bh[nt][1] = *(const uint32_t*)(p + 16);
            bl[nt][0] = *(const uint32_t*)(p + CTILE_B);
            bl[nt][1] = *(const uint32_t*)(p + CTILE_B + 16);
        }
        #pragma unroll
        for (int mt = 0; mt < 4; mt++)
            #pragma unroll
            for (int nt = 0; nt < 2; nt++)
                mma_bf(acc[mt][nt], ah[mt], bh[nt]);
        #pragma unroll
        for (int mt = 0; mt < 4; mt++)
            #pragma unroll
            for (int nt = 0; nt < 2; nt++)
                mma_bf(acc[mt][nt], ah[mt], bl[nt]);
        #pragma unroll
        for (int mt = 0; mt < 4; mt++)
            #pragma unroll
            for (int nt = 0; nt < 2; nt++)
                mma_bf(acc[mt][nt], al[mt], bh[nt]);
    }
}

__global__ void __launch_bounds__(256, 2) ctx_mma_kernel() {
    extern __shared__ char smem[];
    const int tid = threadIdx.x, lane = tid & 31, w = tid >> 5;
    const int wm = w & 1, wn = w >> 1;
    const int bh = blockIdx.y, b_ = bh >> 4, h = bh & 15;
    const int m0 = blockIdx.x * 128;

    const __nv_bfloat16* Ph = g_p_hi + (size_t)bh*SS*SS;
    const __nv_bfloat16* Pl = g_p_lo + (size_t)bh*SS*SS;
    const __nv_bfloat16* Vh = g_vT_hi + (size_t)bh*DD*SS;
    const __nv_bfloat16* Vl = g_vT_lo + (size_t)bh*DD*SS;
    const uint32_t sb = smem_to_u32(smem);

    float acc[4][2][4];
    #pragma unroll
    for (int a = 0; a < 4; a++)
        #pragma unroll
        for (int b = 0; b < 2; b++)
            #pragma unroll
            for (int c = 0; c < 4; c++) acc[a][b][c] = 0.f;

    ctx_load_chunk(sb, tid, Ph, Pl, Vh, Vl, m0, 0);
    ctx_load_chunk(sb + CBUF_B, tid, Ph, Pl, Vh, Vl, m0, 32);
    const int KT = SS / 32;  // 16
    for (int t = 0; t < KT; t++) {
        cp_wait<1>();
        __syncthreads();
        ctx_mma_chunk(smem + (t & 1)*CBUF_B, lane, wm, wn, acc);
        __syncthreads();
        if (t + 2 < KT)
            ctx_load_chunk(sb + (t & 1)*CBUF_B, tid, Ph, Pl, Vh, Vl, m0, (t+2)*32);
        else
            CP_COMMIT();
    }

    const int r0 = lane >> 2, tig = lane & 3;
    #pragma unroll
    for (int mt = 0; mt < 4; mt++)
        #pragma unroll
        for (int nt = 0; nt < 2; nt++) {
            const int d = wn*16 + nt*8 + tig*2;
            #pragma unroll
            for (int rr = 0; rr < 2; rr++) {
                const int m = m0 + wm*64 + mt*16 + r0 + rr*8;
                const float v0 = acc[mt][nt][rr*2];
                const float v1 = acc[mt][nt][rr*2+1];
                const size_t idx = ((size_t)(b_*SS + m))*HH + h*DD + d;
                const __nv_bfloat16 h0 = __float2bfloat16_rn(v0);
                const __nv_bfloat16 h1 = __float2bfloat16_rn(v1);
                const __nv_bfloat16 q0 = __float2bfloat16_rn(v0 - __bfloat162float(h0));
                const __nv_bfloat16 q1 = __float2bfloat16_rn(v1 - __bfloat162float(h1));
                *(uint32_t*)&g_ctx_hi[idx] =
                    ((uint32_t)__bfloat16_as_ushort(h1) << 16) | __bfloat16_as_ushort(h0);
                *(uint32_t*)&g_ctx_lo[idx] =
                    ((uint32_t)__bfloat16_as_ushort(q1) << 16) | __bfloat16_as_ushort(q0);
            }
        }
}

// ============================================================
// Kernel 5: hidden = ctx @ Wd^T + bd, mma bf16x3.
// ============================================================
__global__ void __launch_bounds__(256, 1) final_mma_kernel(
    const float* __restrict__ bias, float* __restrict__ out) {
    extern __shared__ char smem[];
    const int tid = threadIdx.x, lane = tid & 31, w = tid >> 5;
    const int wm = w & 1, wn = w >> 1;
    const int m0 = blockIdx.y * 128, n0 = blockIdx.x * 128;

    const __nv_bfloat16* Ah = g_ctx_hi;
    const __nv_bfloat16* Al = g_ctx_lo;
    const __nv_bfloat16* Bh = g_w_hi + (size_t)7*HH*HH;
    const __nv_bfloat16* Bl = g_w_lo + (size_t)7*HH*HH;
    const uint32_t sb = smem_to_u32(smem);

    float acc[4][4][4];
    #pragma unroll
    for (int a = 0; a < 4; a++)
        #pragma unroll
        for (int b = 0; b < 4; b++)
            #pragma unroll
            for (int c = 0; c < 4; c++) acc[a][b][c] = 0.f;

    load_chunk(sb, tid, Ah, Al, HH, Bh, Bl, HH, m0, n0, 0);
    load_chunk(sb + BUF_B, tid, Ah, Al, HH, Bh, Bl, HH, m0, n0, 32);
    const int KT = HH / 32;
    for (int t = 0; t < KT; t++) {
        cp_wait<1>();
        __syncthreads();
        mma_chunk(smem + (t & 1)*BUF_B, lane, wm, wn, acc);
        __syncthreads();
        if (t + 2 < KT)
            load_chunk(sb + (t & 1)*BUF_B, tid, Ah, Al, HH, Bh, Bl, HH, m0, n0, (t+2)*32);
        else
            CP_COMMIT();
    }

    const int r0 = lane >> 2, tig = lane & 3;
    #pragma unroll
    for (int mt = 0; mt < 4; mt++)
        #pragma unroll
        for (int nt = 0; nt < 4; nt++) {
            const int n = n0 + wn*32 + nt*8 + tig*2;
            const float bv0 = bias[n], bv1 = bias[n+1];
            #pragma unroll
            for (int rr = 0; rr < 2; rr++) {
                const int m = m0 + wm*64 + mt*16 + r0 + rr*8;
                float2 t2 = make_float2(acc[mt][nt][rr*2] + bv0,
                                        acc[mt][nt][rr*2+1] + bv1);
                *(float2*)&out[(size_t)m*HH + n] = t2;
            }
        }
}

// ============================================================
// Launch
// ============================================================
extern "C" void kernel_launch(void* const* d_in, const int* in_sizes, int n_in,
                              void* d_out, int out_size) {
    (void)in_sizes; (void)n_in; (void)out_size;

    const float* query = (const float*)d_in[0];
    const float* key   = (const float*)d_in[1];
    const float* value = (const float*)d_in[2];
    const float* mask  = (const float*)d_in[3];
    const float* pos   = (const float*)d_in[4];
    const float* feat  = (const float*)d_in[5];

    ConvArgs ca;
    ca.src[0] = query; ca.src[1] = key; ca.src[2] = value;
    ca.src[3] = pos;   ca.src[4] = feat;
    for (int i = 0; i < 7; i++) ca.src[5 + i] = (const float*)d_in[6 + 2*i];
    ca.src[12] = (const float*)d_in[20];  // Wd

    TCArgs ta;
    for (int i = 0; i < 7; i++) ta.bias[i] = (const float*)d_in[7 + 2*i];
    const float* bd = (const float*)d_in[21];

    float* out     = (float*)d_out;
    float* hidden  = out;                        // [B,S,H]
    float* attnmap = out + (size_t)MM * HH;      // [B,NH,S,S]

    cudaFuncSetAttribute(proj_mma_kernel,   cudaFuncAttributeMaxDynamicSharedMemorySize, SMEM_B);
    cudaFuncSetAttribute(scores_mma_kernel, cudaFuncAttributeMaxDynamicSharedMemorySize, SMEM_B);
    cudaFuncSetAttribute(final_mma_kernel,  cudaFuncAttributeMaxDynamicSharedMemorySize, SMEM_B);
    cudaFuncSetAttribute(ctx_mma_kernel,    cudaFuncAttributeMaxDynamicSharedMemorySize, CSMEM_B);

    convert_kernel<<<dim3(4096, 1, 13), 256>>>(ca);
    proj_mma_kernel<<<dim3(8, 32, 7), 256, SMEM_B>>>(ta);
    vt_kernel<<<dim3(16, 2, BH), dim3(32, 8)>>>();
    scores_mma_kernel<<<dim3(4, 4, BH), 256, SMEM_B>>>(mask, attnmap);
    softmax_kernel<<<BH * SS, 128>>>();
    ctx_mma_kernel<<<dim3(4, BH), 256, CSMEM_B>>>();
    final_mma_kernel<<<dim3(8, 32), 256, SMEM_B>>>(bd, hidden);
}

// round 5
// speedup vs baseline: 2.1477x; 1.1374x over previous
#include <cuda_runtime.h>
#include <cuda_bf16.h>
#include <math.h>
#include <cstdint>

#define BB 8
#define SS 512
#define HH 1024
#define NHD 16
#define DD 64
#define MM (BB*SS)      // 4096
#define BH (BB*NHD)     // 128
#define CD 192          // concatenated head dim (q|qp|qf)

// ---- scratch (device globals; no allocations allowed) ----
static __device__ __align__(16) float g_v[(size_t)BH*SS*DD];       // [bh][s][64] fp32
static __device__ __align__(16) float g_scores[(size_t)BH*SS*SS];  // [bh][q][k] fp32

static __device__ __align__(16) __nv_bfloat16 g_qcat_hi[(size_t)BH*SS*CD];
static __device__ __align__(16) __nv_bfloat16 g_qcat_lo[(size_t)BH*SS*CD];
static __device__ __align__(16) __nv_bfloat16 g_kcat_hi[(size_t)BH*SS*CD];
static __device__ __align__(16) __nv_bfloat16 g_kcat_lo[(size_t)BH*SS*CD];
static __device__ __align__(16) __nv_bfloat16 g_act_hi[(size_t)5*MM*HH];
static __device__ __align__(16) __nv_bfloat16 g_act_lo[(size_t)5*MM*HH];
static __device__ __align__(16) __nv_bfloat16 g_w_hi[(size_t)8*HH*HH];
static __device__ __align__(16) __nv_bfloat16 g_w_lo[(size_t)8*HH*HH];
static __device__ __align__(16) __nv_bfloat16 g_ctx_hi[(size_t)MM*HH];
static __device__ __align__(16) __nv_bfloat16 g_ctx_lo[(size_t)MM*HH];
static __device__ __align__(16) __nv_bfloat16 g_p_hi[(size_t)BH*SS*SS];   // probs hi
static __device__ __align__(16) __nv_bfloat16 g_p_lo[(size_t)BH*SS*SS];   // probs lo
static __device__ __align__(16) __nv_bfloat16 g_vT_hi[(size_t)BH*DD*SS];  // [bh][d][s]
static __device__ __align__(16) __nv_bfloat16 g_vT_lo[(size_t)BH*DD*SS];

// ---- mma tile geometry (128x128 kernels) ----
#define TILE_B 10240                 // 128*40*2 bytes (row stride 40 halves = 80B)
#define BUF_B  (4*TILE_B)            // 40960
#define SMEM_B (2*BUF_B)             // 81920

// ---- ctx tile geometry (128x64, A=P[128x32k], B=vT[64x32k]) ----
#define CTILE_A 10240                // 128*40*2
#define CTILE_B 5120                 // 64*40*2
#define CBUF_B  (2*CTILE_A + 2*CTILE_B)  // 30720
#define CSMEM_B (2*CBUF_B)               // 61440

__device__ __forceinline__ uint32_t smem_to_u32(const void* p) {
    uint32_t a;
    asm("{ .reg .u64 t; cvta.to.shared.u64 t, %1; cvt.u32.u64 %0, t; }" : "=r"(a) : "l"(p));
    return a;
}
__device__ __forceinline__ void cp16(uint32_t s, const void* g) {
    asm volatile("cp.async.cg.shared.global [%0], [%1], 16;" :: "r"(s), "l"(g));
}
#define CP_COMMIT() asm volatile("cp.async.commit_group;" ::: "memory")
template<int N> __device__ __forceinline__ void cp_wait() {
    asm volatile("cp.async.wait_group %0;" :: "n"(N) : "memory");
}

__device__ __forceinline__ void mma_bf(float* c, const uint32_t* a, const uint32_t* b) {
    asm volatile(
        "mma.sync.aligned.m16n8k16.row.col.f32.bf16.bf16.f32 "
        "{%0,%1,%2,%3}, {%4,%5,%6,%7}, {%8,%9}, {%0,%1,%2,%3};"
        : "+f"(c[0]), "+f"(c[1]), "+f"(c[2]), "+f"(c[3])
        : "r"(a[0]), "r"(a[1]), "r"(a[2]), "r"(a[3]), "r"(b[0]), "r"(b[1]));
}

__device__ __forceinline__ void ldsm_x4(uint32_t* r, uint32_t addr) {
    asm volatile("ldmatrix.sync.aligned.m8n8.x4.shared.b16 {%0,%1,%2,%3}, [%4];"
        : "=r"(r[0]), "=r"(r[1]), "=r"(r[2]), "=r"(r[3]) : "r"(addr));
}

// Load one K-chunk of A(hi,lo) 128 rows and B(hi,lo) 128 rows into one buffer.
__device__ __forceinline__ void load_chunk(uint32_t sbuf, int tid,
    const __nv_bfloat16* __restrict__ Ah, const __nv_bfloat16* __restrict__ Al, int lda,
    const __nv_bfloat16* __restrict__ Bh, const __nv_bfloat16* __restrict__ Bl, int ldb,
    int m0, int n0, int k0) {
    #pragma unroll
    for (int j = 0; j < 2; j++) {
        const int u = tid + 256*j;               // 0..511 uint4 slots
        const int row = u >> 2, cg = (u & 3) * 8;
        const uint32_t so = (uint32_t)(row*40 + cg)*2;
        const size_t ga = (size_t)(m0+row)*lda + k0 + cg;
        const size_t gb = (size_t)(n0+row)*ldb + k0 + cg;
        cp16(sbuf + so,            Ah + ga);
        cp16(sbuf + TILE_B + so,   Al + ga);
        cp16(sbuf + 2*TILE_B + so, Bh + gb);
        cp16(sbuf + 3*TILE_B + so, Bl + gb);
    }
    CP_COMMIT();
}

// One K-chunk of bf16x3 mma. Fragments via ldmatrix.x4 (conflict-free at
// 80B row stride); terms issued term-major (independent accumulators).
__device__ __forceinline__ void mma_chunk(uint32_t buf, int lane, int wm, int wn,
                                          float acc[4][4][4]) {
    const uint32_t l7 = lane & 7, l8 = (lane >> 3) & 1, l16 = (lane >> 4) & 1;
    #pragma unroll
    for (int kk = 0; kk < 2; kk++) {
        const uint32_t colA = kk*32 + l16*16;    // bytes
        const uint32_t colB = kk*32 + l8*16;
        uint32_t ah[4][4], al[4][4], bh[4][2], bl[4][2];
        #pragma unroll
        for (int mt = 0; mt < 4; mt++) {
            const uint32_t row = wm*64 + mt*16 + l7 + l8*8;
            ldsm_x4(ah[mt], buf + row*80 + colA);
            ldsm_x4(al[mt], buf + TILE_B + row*80 + colA);
        }
        #pragma unroll
        for (int np = 0; np < 2; np++) {
            const uint32_t row = wn*32 + np*16 + l7 + l16*8;
            uint32_t t0[4], t1[4];
            ldsm_x4(t0, buf + 2*TILE_B + row*80 + colB);
            ldsm_x4(t1, buf + 3*TILE_B + row*80 + colB);
            bh[2*np][0] = t0[0]; bh[2*np][1] = t0[1];
            bh[2*np+1][0] = t0[2]; bh[2*np+1][1] = t0[3];
            bl[2*np][0] = t1[0]; bl[2*np][1] = t1[1];
            bl[2*np+1][0] = t1[2]; bl[2*np+1][1] = t1[3];
        }
        #pragma unroll
        for (int mt = 0; mt < 4; mt++)
            #pragma unroll
            for (int nt = 0; nt < 4; nt++)
                mma_bf(acc[mt][nt], ah[mt], bh[nt]);
        #pragma unroll
        for (int mt = 0; mt < 4; mt++)
            #pragma unroll
            for (int nt = 0; nt < 4; nt++)
                mma_bf(acc[mt][nt], ah[mt], bl[nt]);
        #pragma unroll
        for (int mt = 0; mt < 4; mt++)
            #pragma unroll
            for (int nt = 0; nt < 4; nt++)
                mma_bf(acc[mt][nt], al[mt], bh[nt]);
    }
}

// ============================================================
// Kernel 0: convert fp32 -> bf16 hi/lo.
// z 0..4: activations (q,k,v,pos,feat); z 5..12: weights (Wq..Wkf,Wd)
// ============================================================
struct ConvArgs { const float* src[13]; };

__global__ void convert_kernel(ConvArgs ca) {
    const int z = blockIdx.z;
    const size_t nvec = (z < 5) ? (size_t)MM*HH/4 : (size_t)HH*HH/4;
    const size_t i = (size_t)blockIdx.x * 256 + threadIdx.x;
    if (i >= nvec) return;
    const float4 v = ((const float4*)ca.src[z])[i];

    __nv_bfloat16 h0 = __float2bfloat16_rn(v.x);
    __nv_bfloat16 h1 = __float2bfloat16_rn(v.y);
    __nv_bfloat16 h2 = __float2bfloat16_rn(v.z);
    __nv_bfloat16 h3 = __float2bfloat16_rn(v.w);
    __nv_bfloat16 l0 = __float2bfloat16_rn(v.x - __bfloat162float(h0));
    __nv_bfloat16 l1 = __float2bfloat16_rn(v.y - __bfloat162float(h1));
    __nv_bfloat16 l2 = __float2bfloat16_rn(v.z - __bfloat162float(h2));
    __nv_bfloat16 l3 = __float2bfloat16_rn(v.w - __bfloat162float(h3));

    __nv_bfloat16 *dh, *dl;
    if (z < 5) { dh = g_act_hi + (size_t)z*MM*HH + i*4; dl = g_act_lo + (size_t)z*MM*HH + i*4; }
    else       { dh = g_w_hi + (size_t)(z-5)*HH*HH + i*4; dl = g_w_lo + (size_t)(z-5)*HH*HH + i*4; }
    *(ushort4*)dh = make_ushort4(__bfloat16_as_ushort(h0), __bfloat16_as_ushort(h1),
                                 __bfloat16_as_ushort(h2), __bfloat16_as_ushort(h3));
    *(ushort4*)dl = make_ushort4(__bfloat16_as_ushort(l0), __bfloat16_as_ushort(l1),
                                 __bfloat16_as_ushort(l2), __bfloat16_as_ushort(l3));
}

// ============================================================
// Kernel 1: 7 fused projections, mma.sync bf16x3, C = A*W^T + b.
// ============================================================
struct TCArgs { const float* bias[7]; };

__global__ void __launch_bounds__(256) proj_mma_kernel(TCArgs ta) {
    extern __shared__ char smem[];
    const int tid = threadIdx.x, lane = tid & 31, w = tid >> 5;
    const int wm = w & 1, wn = w >> 1;
    const int z = blockIdx.z;
    const int ai = (z <= 2) ? z : (z <= 4 ? 3 : 4);
    const int m0 = blockIdx.y * 128, n0 = blockIdx.x * 128;

    const __nv_bfloat16* Ah = g_act_hi + (size_t)ai*MM*HH;
    const __nv_bfloat16* Al = g_act_lo + (size_t)ai*MM*HH;
    const __nv_bfloat16* Bh = g_w_hi + (size_t)z*HH*HH;
    const __nv_bfloat16* Bl = g_w_lo + (size_t)z*HH*HH;
    const uint32_t sb = smem_to_u32(smem);

    float acc[4][4][4];
    #pragma unroll
    for (int a = 0; a < 4; a++)
        #pragma unroll
        for (int b = 0; b < 4; b++)
            #pragma unroll
            for (int c = 0; c < 4; c++) acc[a][b][c] = 0.f;

    load_chunk(sb, tid, Ah, Al, HH, Bh, Bl, HH, m0, n0, 0);
    load_chunk(sb + BUF_B, tid, Ah, Al, HH, Bh, Bl, HH, m0, n0, 32);
    const int KT = HH / 32;  // 32
    for (int t = 0; t < KT; t++) {
        cp_wait<1>();
        __syncthreads();
        mma_chunk(sb + (t & 1)*BUF_B, lane, wm, wn, acc);
        __syncthreads();
        if (t + 2 < KT)
            load_chunk(sb + (t & 1)*BUF_B, tid, Ah, Al, HH, Bh, Bl, HH, m0, n0, (t+2)*32);
        else
            CP_COMMIT();
    }

    int od0 = 0;
    __nv_bfloat16 *dh = nullptr, *dl = nullptr;
    switch (z) {
        case 0: dh = g_qcat_hi; dl = g_qcat_lo; od0 = 0;   break;
        case 1: dh = g_kcat_hi; dl = g_kcat_lo; od0 = 0;   break;
        case 2: break;  // v -> fp32
        case 3: dh = g_qcat_hi; dl = g_qcat_lo; od0 = 64;  break;
        case 4: dh = g_kcat_hi; dl = g_kcat_lo; od0 = 64;  break;
        case 5: dh = g_qcat_hi; dl = g_qcat_lo; od0 = 128; break;
        default: dh = g_kcat_hi; dl = g_kcat_lo; od0 = 128; break;
    }
    const float* bias = ta.bias[z];
    const int r0 = lane >> 2, tig = lane & 3;
    #pragma unroll
    for (int mt = 0; mt < 4; mt++)
        #pragma unroll
        for (int nt = 0; nt < 4; nt++) {
            const int n = n0 + wn*32 + nt*8 + tig*2;
            const float bv0 = bias[n], bv1 = bias[n+1];
            const int h = n >> 6, d = n & 63;
            #pragma unroll
            for (int rr = 0; rr < 2; rr++) {
                const int m = m0 + wm*64 + mt*16 + r0 + rr*8;
                const int b_ = m >> 9, s = m & 511;
                const float v0 = acc[mt][nt][rr*2]   + bv0;
                const float v1 = acc[mt][nt][rr*2+1] + bv1;
                if (z == 2) {
                    float2 t2 = make_float2(v0, v1);
                    *(float2*)&g_v[((size_t)((b_*NHD + h)*SS + s))*DD + d] = t2;
                } else {
                    const size_t idx = ((size_t)((b_*NHD + h)*SS + s))*CD + od0 + d;
                    __nv_bfloat16 h0 = __float2bfloat16_rn(v0);
                    __nv_bfloat16 h1 = __float2bfloat16_rn(v1);
                    __nv_bfloat16 q0 = __float2bfloat16_rn(v0 - __bfloat162float(h0));
                    __nv_bfloat16 q1 = __float2bfloat16_rn(v1 - __bfloat162float(h1));
                    *(uint32_t*)&dh[idx] =
                        ((uint32_t)__bfloat16_as_ushort(h1) << 16) | __bfloat16_as_ushort(h0);
                    *(uint32_t*)&dl[idx] =
                        ((uint32_t)__bfloat16_as_ushort(q1) << 16) | __bfloat16_as_ushort(q0);
                }
            }
        }
}

// ============================================================
// Kernel 1b: V transpose + hi/lo convert: g_v [bh][s][d] fp32
//            -> g_vT_{hi,lo} [bh][d][s] bf16.
// ============================================================
__global__ void vt_kernel() {
    __shared__ float t[32][33];
    const int bh = blockIdx.z;
    const int s0 = blockIdx.x * 32, d0 = blockIdx.y * 32;
    const int tx = threadIdx.x, ty = threadIdx.y;
    const float* src = g_v + (size_t)bh*SS*DD;
    #pragma unroll
    for (int i = 0; i < 4; i++)
        t[ty + i*8][tx] = src[(size_t)(s0 + ty + i*8)*DD + d0 + tx];
    __syncthreads();
    #pragma unroll
    for (int i = 0; i < 4; i++) {
        const int d = d0 + ty + i*8, s = s0 + tx;
        const float v = t[tx][ty + i*8];
        const __nv_bfloat16 h = __float2bfloat16_rn(v);
        const __nv_bfloat16 l = __float2bfloat16_rn(v - __bfloat162float(h));
        g_vT_hi[(size_t)(bh*DD + d)*SS + s] = h;
        g_vT_lo[(size_t)(bh*DD + d)*SS + s] = l;
    }
}

// ============================================================
// Kernel 2: scores per (b,h): [512x512 x K=192] mma bf16x3,
// snapshot at K=64 -> attention_map; final scores = acc/8 + mask.
// ============================================================
__global__ void __launch_bounds__(256) scores_mma_kernel(
    const float* __restrict__ mask, float* __restrict__ attnmap) {
    extern __shared__ char smem[];
    const int tid = threadIdx.x, lane = tid & 31, w = tid >> 5;
    const int wm = w & 1, wn = w >> 1;
    const int bh = blockIdx.z, b_ = bh >> 4;
    const int m0 = blockIdx.y * 128, n0 = blockIdx.x * 128;

    const __nv_bfloat16* Ah = g_qcat_hi + (size_t)bh*SS*CD;
    const __nv_bfloat16* Al = g_qcat_lo + (size_t)bh*SS*CD;
    const __nv_bfloat16* Bh = g_kcat_hi + (size_t)bh*SS*CD;
    const __nv_bfloat16* Bl = g_kcat_lo + (size_t)bh*SS*CD;
    const uint32_t sb = smem_to_u32(smem);
    const int r0 = lane >> 2, tig = lane & 3;

    float acc[4][4][4];
    #pragma unroll
    for (int a = 0; a < 4; a++)
        #pragma unroll
        for (int b = 0; b < 4; b++)
            #pragma unroll
            for (int c = 0; c < 4; c++) acc[a][b][c] = 0.f;

    load_chunk(sb, tid, Ah, Al, CD, Bh, Bl, CD, m0, n0, 0);
    load_chunk(sb + BUF_B, tid, Ah, Al, CD, Bh, Bl, CD, m0, n0, 32);
    const int KT = CD / 32;  // 6
    for (int t = 0; t < KT; t++) {
        cp_wait<1>();
        __syncthreads();
        mma_chunk(sb + (t & 1)*BUF_B, lane, wm, wn, acc);
        if (t == 1) {  // content part (K=0..63) complete -> attention_map
            float* amb = attnmap + (size_t)bh*SS*SS;
            #pragma unroll
            for (int mt = 0; mt < 4; mt++)
                #pragma unroll
                for (int nt = 0; nt < 4; nt++) {
                    const int n = n0 + wn*32 + nt*8 + tig*2;
                    #pragma unroll
                    for (int rr = 0; rr < 2; rr++) {
                        const int m = m0 + wm*64 + mt*16 + r0 + rr*8;
                        float2 t2 = make_float2(acc[mt][nt][rr*2], acc[mt][nt][rr*2+1]);
                        *(float2*)&amb[(size_t)m*SS + n] = t2;
                    }
                }
        }
        __syncthreads();
        if (t + 2 < KT)
            load_chunk(sb + (t & 1)*BUF_B, tid, Ah, Al, CD, Bh, Bl, CD, m0, n0, (t+2)*32);
        else
            CP_COMMIT();
    }

    float* scb = g_scores + (size_t)bh*SS*SS;
    #pragma unroll
    for (int mt = 0; mt < 4; mt++)
        #pragma unroll
        for (int nt = 0; nt < 4; nt++) {
            const int n = n0 + wn*32 + nt*8 + tig*2;
            #pragma unroll
            for (int rr = 0; rr < 2; rr++) {
                const int m = m0 + wm*64 + mt*16 + r0 + rr*8;
                const float2 mk = *(const float2*)&mask[((size_t)b_*SS + m)*SS + n];
                float2 t2 = make_float2(acc[mt][nt][rr*2]*0.125f + mk.x,
                                        acc[mt][nt][rr*2+1]*0.125f + mk.y);
                *(float2*)&scb[(size_t)m*SS + n] = t2;
            }
        }
}

// ============================================================
// Kernel 3: row softmax on g_scores -> g_p_{hi,lo} bf16.
// ============================================================
__global__ void softmax_kernel() {
    const size_t r = blockIdx.x;
    const float* row = g_scores + r * SS;
    float4 v = ((const float4*)row)[threadIdx.x];

    float mx = fmaxf(fmaxf(v.x, v.y), fmaxf(v.z, v.w));
    #pragma unroll
    for (int o = 16; o; o >>= 1) mx = fmaxf(mx, __shfl_xor_sync(0xffffffffu, mx, o));
    __shared__ float sm[4];
    const int w = threadIdx.x >> 5;
    if ((threadIdx.x & 31) == 0) sm[w] = mx;
    __syncthreads();
    mx = fmaxf(fmaxf(sm[0], sm[1]), fmaxf(sm[2], sm[3]));

    v.x = expf(v.x - mx); v.y = expf(v.y - mx);
    v.z = expf(v.z - mx); v.w = expf(v.w - mx);
    float s = v.x + v.y + v.z + v.w;
    #pragma unroll
    for (int o = 16; o; o >>= 1) s += __shfl_xor_sync(0xffffffffu, s, o);
    __shared__ float ss[4];
    if ((threadIdx.x & 31) == 0) ss[w] = s;
    __syncthreads();
    s = ss[0] + ss[1] + ss[2] + ss[3];

    const float inv = 1.f / s;
    v.x *= inv; v.y *= inv; v.z *= inv; v.w *= inv;

    const __nv_bfloat16 h0 = __float2bfloat16_rn(v.x);
    const __nv_bfloat16 h1 = __float2bfloat16_rn(v.y);
    const __nv_bfloat16 h2 = __float2bfloat16_rn(v.z);
    const __nv_bfloat16 h3 = __float2bfloat16_rn(v.w);
    const __nv_bfloat16 l0 = __float2bfloat16_rn(v.x - __bfloat162float(h0));
    const __nv_bfloat16 l1 = __float2bfloat16_rn(v.y - __bfloat162float(h1));
    const __nv_bfloat16 l2 = __float2bfloat16_rn(v.z - __bfloat162float(h2));
    const __nv_bfloat16 l3 = __float2bfloat16_rn(v.w - __bfloat162float(h3));
    ((ushort4*)(g_p_hi + r*SS))[threadIdx.x] =
        make_ushort4(__bfloat16_as_ushort(h0), __bfloat16_as_ushort(h1),
                     __bfloat16_as_ushort(h2), __bfloat16_as_ushort(h3));
    ((ushort4*)(g_p_lo + r*SS))[threadIdx.x] =
        make_ushort4(__bfloat16_as_ushort(l0), __bfloat16_as_ushort(l1),
                     __bfloat16_as_ushort(l2), __bfloat16_as_ushort(l3));
}

// ============================================================
// Kernel 4: ctx = P @ V via mma bf16x3. Per (bh): A=P[512x512],
// B=vT[64x512]. Tile 128x64, K-chunk 32. Writes ctx hi/lo bf16.
// ============================================================
__device__ __forceinline__ void ctx_load_chunk(uint32_t sbuf, int tid,
    const __nv_bfloat16* __restrict__ Ph, const __nv_bfloat16* __restrict__ Pl,
    const __nv_bfloat16* __restrict__ Vh, const __nv_bfloat16* __restrict__ Vl,
    int m0, int k0) {
    #pragma unroll
    for (int j = 0; j < 2; j++) {
        const int u = tid + 256*j;               // 0..511
        const int row = u >> 2, cg = (u & 3) * 8;
        const uint32_t so = (uint32_t)(row*40 + cg)*2;
        const size_t ga = (size_t)(m0+row)*SS + k0 + cg;
        cp16(sbuf + so,           Ph + ga);
        cp16(sbuf + CTILE_A + so, Pl + ga);
    }
    {
        const int u = tid;                        // 0..255
        const int row = u >> 2, cg = (u & 3) * 8;
        const uint32_t so = (uint32_t)(row*40 + cg)*2;
        const size_t gb = (size_t)row*SS + k0 + cg;
        cp16(sbuf + 2*CTILE_A + so,           Vh + gb);
        cp16(sbuf + 2*CTILE_A + CTILE_B + so, Vl + gb);
    }
    CP_COMMIT();
}

__device__ __forceinline__ void ctx_mma_chunk(uint32_t buf, int lane, int wm, int wn,
                                              float acc[4][2][4]) {
    const uint32_t l7 = lane & 7, l8 = (lane >> 3) & 1, l16 = (lane >> 4) & 1;
    #pragma unroll
    for (int kk = 0; kk < 2; kk++) {
        const uint32_t colA = kk*32 + l16*16;
        const uint32_t colB = kk*32 + l8*16;
        uint32_t ah[4][4], al[4][4], bh[2][2], bl[2][2];
        #pragma unroll
        for (int mt = 0; mt < 4; mt++) {
            const uint32_t row = wm*64 + mt*16 + l7 + l8*8;
            ldsm_x4(ah[mt], buf + row*80 + colA);
            ldsm_x4(al[mt], buf + CTILE_A + row*80 + colA);
        }
        {
            const uint32_t row = wn*16 + l7 + l16*8;
            uint32_t t0[4], t1[4];
            ldsm_x4(t0, buf + 2*CTILE_A + row*80 + colB);
            ldsm_x4(t1, buf + 2*CTILE_A + CTILE_B + row*80 + colB);
            bh[0][0] = t0[0]; bh[0][1] = t0[1]; bh[1][0] = t0[2]; bh[1][1] = t0[3];
            bl[0][0] = t1[0]; bl[0][1] = t1[1]; bl[1][0] = t1[2]; bl[1][1] = t1[3];
        }
        #pragma unroll
        for (int mt = 0; mt < 4; mt++)
            #pragma unroll
            for (int nt = 0; nt < 2; nt++)
                mma_bf(acc[mt][nt], ah[mt], bh[nt]);
        #pragma unroll
        for (int mt = 0; mt < 4; mt++)
            #pragma unroll
            for (int nt = 0; nt < 2; nt++)
                mma_bf(acc[mt][nt], ah[mt], bl[nt]);
        #pragma unroll
        for (int mt = 0; mt < 4; mt++)
            #pragma unroll
            for (int nt = 0; nt < 2; nt++)
                mma_bf(acc[mt][nt], al[mt], bh[nt]);
    }
}

__global__ void __launch_bounds__(256) ctx_mma_kernel() {
    extern __shared__ char smem[];
    const int tid = threadIdx.x, lane = tid & 31, w = tid >> 5;
    const int wm = w & 1, wn = w >> 1;
    const int bh = blockIdx.y, b_ = bh >> 4, h = bh & 15;
    const int m0 = blockIdx.x * 128;

    const __nv_bfloat16* Ph = g_p_hi + (size_t)bh*SS*SS;
    const __nv_bfloat16* Pl = g_p_lo + (size_t)bh*SS*SS;
    const __nv_bfloat16* Vh = g_vT_hi + (size_t)bh*DD*SS;
    const __nv_bfloat16* Vl = g_vT_lo + (size_t)bh*DD*SS;
    const uint32_t sb = smem_to_u32(smem);

    float acc[4][2][4];
    #pragma unroll
    for (int a = 0; a < 4; a++)
        #pragma unroll
        for (int b = 0; b < 2; b++)
            #pragma unroll
            for (int c = 0; c < 4; c++) acc[a][b][c] = 0.f;

    ctx_load_chunk(sb, tid, Ph, Pl, Vh, Vl, m0, 0);
    ctx_load_chunk(sb + CBUF_B, tid, Ph, Pl, Vh, Vl, m0, 32);
    const int KT = SS / 32;  // 16
    for (int t = 0; t < KT; t++) {
        cp_wait<1>();
        __syncthreads();
        ctx_mma_chunk(sb + (t & 1)*CBUF_B, lane, wm, wn, acc);
        __syncthreads();
        if (t + 2 < KT)
            ctx_load_chunk(sb + (t & 1)*CBUF_B, tid, Ph, Pl, Vh, Vl, m0, (t+2)*32);
        else
            CP_COMMIT();
    }

    const int r0 = lane >> 2, tig = lane & 3;
    #pragma unroll
    for (int mt = 0; mt < 4; mt++)
        #pragma unroll
        for (int nt = 0; nt < 2; nt++) {
            const int d = wn*16 + nt*8 + tig*2;
            #pragma unroll
            for (int rr = 0; rr < 2; rr++) {
                const int m = m0 + wm*64 + mt*16 + r0 + rr*8;
                const float v0 = acc[mt][nt][rr*2];
                const float v1 = acc[mt][nt][rr*2+1];
                const size_t idx = ((size_t)(b_*SS + m))*HH + h*DD + d;
                const __nv_bfloat16 h0 = __float2bfloat16_rn(v0);
                const __nv_bfloat16 h1 = __float2bfloat16_rn(v1);
                const __nv_bfloat16 q0 = __float2bfloat16_rn(v0 - __bfloat162float(h0));
                const __nv_bfloat16 q1 = __float2bfloat16_rn(v1 - __bfloat162float(h1));
                *(uint32_t*)&g_ctx_hi[idx] =
                    ((uint32_t)__bfloat16_as_ushort(h1) << 16) | __bfloat16_as_ushort(h0);
                *(uint32_t*)&g_ctx_lo[idx] =
                    ((uint32_t)__bfloat16_as_ushort(q1) << 16) | __bfloat16_as_ushort(q0);
            }
        }
}

// ============================================================
// Kernel 5: hidden = ctx @ Wd^T + bd, mma bf16x3.
// ============================================================
__global__ void __launch_bounds__(256) final_mma_kernel(
    const float* __restrict__ bias, float* __restrict__ out) {
    extern __shared__ char smem[];
    const int tid = threadIdx.x, lane = tid & 31, w = tid >> 5;
    const int wm = w & 1, wn = w >> 1;
    const int m0 = blockIdx.y * 128, n0 = blockIdx.x * 128;

    const __nv_bfloat16* Ah = g_ctx_hi;
    const __nv_bfloat16* Al = g_ctx_lo;
    const __nv_bfloat16* Bh = g_w_hi + (size_t)7*HH*HH;
    const __nv_bfloat16* Bl = g_w_lo + (size_t)7*HH*HH;
    const uint32_t sb = smem_to_u32(smem);

    float acc[4][4][4];
    #pragma unroll
    for (int a = 0; a < 4; a++)
        #pragma unroll
        for (int b = 0; b < 4; b++)
            #pragma unroll
            for (int c = 0; c < 4; c++) acc[a][b][c] = 0.f;

    load_chunk(sb, tid, Ah, Al, HH, Bh, Bl, HH, m0, n0, 0);
    load_chunk(sb + BUF_B, tid, Ah, Al, HH, Bh, Bl, HH, m0, n0, 32);
    const int KT = HH / 32;
    for (int t = 0; t < KT; t++) {
        cp_wait<1>();
        __syncthreads();
        mma_chunk(sb + (t & 1)*BUF_B, lane, wm, wn, acc);
        __syncthreads();
        if (t + 2 < KT)
            load_chunk(sb + (t & 1)*BUF_B, tid, Ah, Al, HH, Bh, Bl, HH, m0, n0, (t+2)*32);
        else
            CP_COMMIT();
    }

    const int r0 = lane >> 2, tig = lane & 3;
    #pragma unroll
    for (int mt = 0; mt < 4; mt++)
        #pragma unroll
        for (int nt = 0; nt < 4; nt++) {
            const int n = n0 + wn*32 + nt*8 + tig*2;
            const float bv0 = bias[n], bv1 = bias[n+1];
            #pragma unroll
            for (int rr = 0; rr < 2; rr++) {
                const int m = m0 + wm*64 + mt*16 + r0 + rr*8;
                float2 t2 = make_float2(acc[mt][nt][rr*2] + bv0,
                                        acc[mt][nt][rr*2+1] + bv1);
                *(float2*)&out[(size_t)m*HH + n] = t2;
            }
        }
}

// ============================================================
// Launch
// ============================================================
extern "C" void kernel_launch(void* const* d_in, const int* in_sizes, int n_in,
                              void* d_out, int out_size) {
    (void)in_sizes; (void)n_in; (void)out_size;

    const float* query = (const float*)d_in[0];
    const float* key   = (const float*)d_in[1];
    const float* value = (const float*)d_in[2];
    const float* mask  = (const float*)d_in[3];
    const float* pos   = (const float*)d_in[4];
    const float* feat  = (const float*)d_in[5];

    ConvArgs ca;
    ca.src[0] = query; ca.src[1] = key; ca.src[2] = value;
    ca.src[3] = pos;   ca.src[4] = feat;
    for (int i = 0; i < 7; i++) ca.src[5 + i] = (const float*)d_in[6 + 2*i];
    ca.src[12] = (const float*)d_in[20];  // Wd

    TCArgs ta;
    for (int i = 0; i < 7; i++) ta.bias[i] = (const float*)d_in[7 + 2*i];
    const float* bd = (const float*)d_in[21];

    float* out     = (float*)d_out;
    float* hidden  = out;                        // [B,S,H]
    float* attnmap = out + (size_t)MM * HH;      // [B,NH,S,S]

    cudaFuncSetAttribute(proj_mma_kernel,   cudaFuncAttributeMaxDynamicSharedMemorySize, SMEM_B);
    cudaFuncSetAttribute(scores_mma_kernel, cudaFuncAttributeMaxDynamicSharedMemorySize, SMEM_B);
    cudaFuncSetAttribute(final_mma_kernel,  cudaFuncAttributeMaxDynamicSharedMemorySize, SMEM_B);
    cudaFuncSetAttribute(ctx_mma_kernel,    cudaFuncAttributeMaxDynamicSharedMemorySize, CSMEM_B);

    convert_kernel<<<dim3(4096, 1, 13), 256>>>(ca);
    proj_mma_kernel<<<dim3(8, 32, 7), 256, SMEM_B>>>(ta);
    vt_kernel<<<dim3(16, 2, BH), dim3(32, 8)>>>();
    scores_mma_kernel<<<dim3(4, 4, BH), 256, SMEM_B>>>(mask, attnmap);
    softmax_kernel<<<BH * SS, 128>>>();
    ctx_mma_kernel<<<dim3(4, BH), 256, CSMEM_B>>>();
    final_mma_kernel<<<dim3(8, 32), 256, SMEM_B>>>(bd, hidden);
}